// round 1
// baseline (speedup 1.0000x reference)
#include <cuda_runtime.h>
#include <cstdint>

#define NUSR 100000
#define NBIZ 20000
#define EUB  3200000
#define EUU  1600000
#define EBB  320000
#define INDIM 384
#define D    128

// ---------------- scratch (allocation-free: static device globals) ----------
__device__ float g_uA[(size_t)NUSR * D];
__device__ float g_uB[(size_t)NUSR * D];
__device__ float g_uS[(size_t)NUSR * D];
__device__ float g_bA[(size_t)NBIZ * D];
__device__ float g_bB[(size_t)NBIZ * D];
__device__ float g_bS[(size_t)NBIZ * D];

// ---------------- helpers ----------------------------------------------------
__device__ __forceinline__ void red_add_v4(float* p, float4 v) {
    asm volatile("red.global.add.v4.f32 [%0], {%1,%2,%3,%4};"
                 :: "l"(p), "f"(v.x), "f"(v.y), "f"(v.z), "f"(v.w)
                 : "memory");
}

// ---------------- dense GEMM: C[M,128] = A[M,384] @ W[384,128] ---------------
// BM=64, BN=128, BK=8; 256 threads; 8x4 micro-tile per thread.
__global__ void gemm_kernel(const float* __restrict__ A,
                            const float* __restrict__ W,
                            float* __restrict__ C, int M) {
    __shared__ float As[8][64];
    __shared__ float Ws[8][128];
    const int block_row = blockIdx.x * 64;
    const int tid  = threadIdx.x;
    const int tcol = tid & 31;   // col group: cols tcol*4 .. tcol*4+3
    const int trow = tid >> 5;   // row group: rows trow*8 .. trow*8+7

    float acc[8][4];
#pragma unroll
    for (int i = 0; i < 8; i++)
#pragma unroll
        for (int j = 0; j < 4; j++) acc[i][j] = 0.f;

    for (int k0 = 0; k0 < INDIM; k0 += 8) {
        // load A tile: 64 rows x 8 k  (512 elems / 256 threads = 2 each)
#pragma unroll
        for (int i = 0; i < 2; i++) {
            int idx = tid + i * 256;     // 0..511
            int r  = idx >> 3;
            int kk = idx & 7;
            int gr = block_row + r;
            As[kk][r] = (gr < M) ? A[(size_t)gr * INDIM + k0 + kk] : 0.f;
        }
        // load W tile: 8 k x 128 cols (1024 elems / 256 threads = 4 each)
#pragma unroll
        for (int i = 0; i < 4; i++) {
            int idx = tid + i * 256;     // 0..1023
            int kk = idx >> 7;
            int c  = idx & 127;
            Ws[kk][c] = W[(size_t)(k0 + kk) * D + c];
        }
        __syncthreads();
#pragma unroll
        for (int kk = 0; kk < 8; kk++) {
            float b[4];
#pragma unroll
            for (int j = 0; j < 4; j++) b[j] = Ws[kk][tcol * 4 + j];
#pragma unroll
            for (int i = 0; i < 8; i++) {
                float a = As[kk][trow * 8 + i];
#pragma unroll
                for (int j = 0; j < 4; j++) acc[i][j] += a * b[j];
            }
        }
        __syncthreads();
    }
#pragma unroll
    for (int i = 0; i < 8; i++) {
        int gr = block_row + trow * 8 + i;
        if (gr < M) {
            float4 v = make_float4(acc[i][0], acc[i][1], acc[i][2], acc[i][3]);
            *reinterpret_cast<float4*>(C + (size_t)gr * D + tcol * 4) = v;
        }
    }
}

// ---------------- bipartite SpMM (both directions per edge) ------------------
// per warp: one UB edge. gather u row & b row (512B each, coalesced),
// scatter val_ub*u -> b_new[b], val_bu*b -> u_new[u]  via red.v4
__global__ void spmm_ub_kernel(const int* __restrict__ ub_u,
                               const int* __restrict__ ub_b,
                               const float* __restrict__ val_ub,
                               const float* __restrict__ val_bu,
                               const float* __restrict__ u_cur,
                               const float* __restrict__ b_cur,
                               float* __restrict__ u_new,
                               float* __restrict__ b_new) {
    const int lane = threadIdx.x & 31;
    const int e    = (blockIdx.x * blockDim.x + threadIdx.x) >> 5;
    if (e >= EUB) return;
    const int u = __ldg(ub_u + e);
    const int b = __ldg(ub_b + e);
    const float vub = __ldg(val_ub + e);
    const float vbu = __ldg(val_bu + e);

    float4 uv = reinterpret_cast<const float4*>(u_cur + (size_t)u * D)[lane];
    float4 bv = reinterpret_cast<const float4*>(b_cur + (size_t)b * D)[lane];

    float4 to_b = make_float4(uv.x * vub, uv.y * vub, uv.z * vub, uv.w * vub);
    float4 to_u = make_float4(bv.x * vbu, bv.y * vbu, bv.z * vbu, bv.w * vbu);

    red_add_v4(b_new + (size_t)b * D + lane * 4, to_b);
    red_add_v4(u_new + (size_t)u * D + lane * 4, to_u);
}

// ---------------- homogeneous SpMM (uu or bb) --------------------------------
__global__ void spmm_same_kernel(const int* __restrict__ src,
                                 const int* __restrict__ dst,
                                 const float* __restrict__ val,
                                 const float* __restrict__ x,
                                 float* __restrict__ y, int E) {
    const int lane = threadIdx.x & 31;
    const int e    = (blockIdx.x * blockDim.x + threadIdx.x) >> 5;
    if (e >= E) return;
    const int s = __ldg(src + e);
    const int d = __ldg(dst + e);
    const float v = __ldg(val + e);
    float4 xv = reinterpret_cast<const float4*>(x + (size_t)s * D)[lane];
    float4 sv = make_float4(xv.x * v, xv.y * v, xv.z * v, xv.w * v);
    red_add_v4(y + (size_t)d * D + lane * 4, sv);
}

// ---------------- running-sum accumulate: s += x (float4) --------------------
__global__ void acc_kernel(float* __restrict__ s, const float* __restrict__ x,
                           int n4) {
    int i = blockIdx.x * blockDim.x + threadIdx.x;
    if (i >= n4) return;
    float4 a = reinterpret_cast<float4*>(s)[i];
    float4 b = reinterpret_cast<const float4*>(x)[i];
    a.x += b.x; a.y += b.y; a.z += b.z; a.w += b.w;
    reinterpret_cast<float4*>(s)[i] = a;
}

// ---------------- epilogue: out = l2norm(sum * inv) --------------------------
__global__ void l2norm_kernel(const float* __restrict__ s,
                              float* __restrict__ out, int nrows, float inv) {
    const int lane = threadIdx.x & 31;
    const int row  = (blockIdx.x * blockDim.x + threadIdx.x) >> 5;
    if (row >= nrows) return;
    float4 v = reinterpret_cast<const float4*>(s + (size_t)row * D)[lane];
    v.x *= inv; v.y *= inv; v.z *= inv; v.w *= inv;
    float ss = v.x * v.x + v.y * v.y + v.z * v.z + v.w * v.w;
#pragma unroll
    for (int o = 16; o; o >>= 1) ss += __shfl_xor_sync(0xffffffffu, ss, o);
    float nrm = sqrtf(ss);
    float sc = 1.0f / fmaxf(nrm, 1e-12f);
    v.x *= sc; v.y *= sc; v.z *= sc; v.w *= sc;
    reinterpret_cast<float4*>(out + (size_t)row * D)[lane] = v;
}

// ---------------- launcher ----------------------------------------------------
extern "C" void kernel_launch(void* const* d_in, const int* in_sizes, int n_in,
                              void* d_out, int out_size) {
    const float* user_feat = (const float*)d_in[0];
    const float* biz_feat  = (const float*)d_in[1];
    const float* W_user    = (const float*)d_in[2];
    const float* W_biz     = (const float*)d_in[3];
    const int*   ub_u      = (const int*)  d_in[4];
    const int*   ub_b      = (const int*)  d_in[5];
    const float* val_ub    = (const float*)d_in[6];
    const float* val_bu    = (const float*)d_in[7];
    const int*   uu_src    = (const int*)  d_in[8];
    const int*   uu_dst    = (const int*)  d_in[9];
    const float* uu_val    = (const float*)d_in[10];
    const int*   bb_src    = (const int*)  d_in[11];
    const int*   bb_dst    = (const int*)  d_in[12];
    const float* bb_val    = (const float*)d_in[13];
    float* out = (float*)d_out;

    float *uA, *uB, *uS, *bA, *bB, *bS;
    cudaGetSymbolAddress((void**)&uA, g_uA);
    cudaGetSymbolAddress((void**)&uB, g_uB);
    cudaGetSymbolAddress((void**)&uS, g_uS);
    cudaGetSymbolAddress((void**)&bA, g_bA);
    cudaGetSymbolAddress((void**)&bB, g_bB);
    cudaGetSymbolAddress((void**)&bS, g_bS);

    const size_t uBytes = (size_t)NUSR * D * sizeof(float);
    const size_t bBytes = (size_t)NBIZ * D * sizeof(float);

    // layer 0 embeddings
    gemm_kernel<<<(NUSR + 63) / 64, 256>>>(user_feat, W_user, uA, NUSR);
    gemm_kernel<<<(NBIZ + 63) / 64, 256>>>(biz_feat,  W_biz,  bA, NBIZ);

    // running sums start at layer-0 output
    cudaMemcpyAsync(uS, uA, uBytes, cudaMemcpyDeviceToDevice);
    cudaMemcpyAsync(bS, bA, bBytes, cudaMemcpyDeviceToDevice);

    float* u_cur = uA; float* u_new = uB;
    float* b_cur = bA; float* b_new = bB;

    const int ubBlocks = (EUB * 32 + 255) / 256;
    const int uuBlocks = (EUU * 32 + 255) / 256;
    const int bbBlocks = (EBB * 32 + 255) / 256;
    const int un4 = NUSR * D / 4;
    const int bn4 = NBIZ * D / 4;

    for (int layer = 0; layer < 3; layer++) {
        cudaMemsetAsync(u_new, 0, uBytes);
        cudaMemsetAsync(b_new, 0, bBytes);

        spmm_ub_kernel<<<ubBlocks, 256>>>(ub_u, ub_b, val_ub, val_bu,
                                          u_cur, b_cur, u_new, b_new);
        spmm_same_kernel<<<uuBlocks, 256>>>(uu_src, uu_dst, uu_val,
                                            u_cur, u_new, EUU);
        spmm_same_kernel<<<bbBlocks, 256>>>(bb_src, bb_dst, bb_val,
                                            b_cur, b_new, EBB);

        acc_kernel<<<(un4 + 255) / 256, 256>>>(uS, u_new, un4);
        acc_kernel<<<(bn4 + 255) / 256, 256>>>(bS, b_new, bn4);

        // ping-pong
        float* t;
        t = u_cur; u_cur = u_new; u_new = t;
        t = b_cur; b_cur = b_new; b_new = t;
    }

    const float inv = 1.0f / 4.0f;
    l2norm_kernel<<<(NUSR * 32 + 255) / 256, 256>>>(uS, out, NUSR, inv);
    l2norm_kernel<<<(NBIZ * 32 + 255) / 256, 256>>>(bS, out + (size_t)NUSR * D,
                                                    NBIZ, inv);
    (void)n_in; (void)in_sizes; (void)out_size;
}

// round 2
// speedup vs baseline: 2.0466x; 2.0466x over previous
#include <cuda_runtime.h>
#include <cstdint>

#define NUSR 100000
#define NBIZ 20000
#define EUB  3200000
#define EUU  1600000
#define EBB  320000
#define INDIM 384
#define D    128

// ---------------- scratch (allocation-free: static device globals) ----------
__device__ float g_uA[(size_t)NUSR * D];
__device__ float g_uB[(size_t)NUSR * D];
__device__ float g_uS[(size_t)NUSR * D];
__device__ float g_bA[(size_t)NBIZ * D];
__device__ float g_bB[(size_t)NBIZ * D];
__device__ float g_bS[(size_t)NBIZ * D];

// CSR storage: bu (dst=user, src=biz), uu (dst=user), ub (dst=biz, src=user), bb (dst=biz)
__device__ int   g_bu_ptr[NUSR + 1];
__device__ int   g_bu_col[EUB];
__device__ float g_bu_val[EUB];
__device__ int   g_uu_ptr[NUSR + 1];
__device__ int   g_uu_col[EUU];
__device__ float g_uu_val[EUU];
__device__ int   g_ub_ptr[NBIZ + 1];
__device__ int   g_ub_col[EUB];
__device__ float g_ub_val[EUB];
__device__ int   g_bb_ptr[NBIZ + 1];
__device__ int   g_bb_col[EBB];
__device__ float g_bb_val[EBB];
__device__ int   g_cnt[NUSR];        // reused histogram / cursor
__device__ int   g_part[128];        // scan partials

// ================= CSR build =================================================
__global__ void hist_kernel(const int* __restrict__ dst, int* __restrict__ cnt,
                            int E) {
    int i = blockIdx.x * blockDim.x + threadIdx.x;
    if (i < E) atomicAdd(&cnt[dst[i]], 1);
}

#define SCAN_BLK 1024
__global__ void scan1_kernel(const int* __restrict__ cnt, int* __restrict__ out,
                             int* __restrict__ partials, int n) {
    __shared__ int sh[SCAN_BLK];
    int i = blockIdx.x * SCAN_BLK + threadIdx.x;
    int v = (i < n) ? cnt[i] : 0;
    sh[threadIdx.x] = v;
    __syncthreads();
#pragma unroll
    for (int off = 1; off < SCAN_BLK; off <<= 1) {
        int t = (threadIdx.x >= off) ? sh[threadIdx.x - off] : 0;
        __syncthreads();
        sh[threadIdx.x] += t;
        __syncthreads();
    }
    if (i < n) out[i] = sh[threadIdx.x] - v;  // exclusive
    if (threadIdx.x == SCAN_BLK - 1) partials[blockIdx.x] = sh[threadIdx.x];
}

__global__ void scan2_kernel(int* __restrict__ partials, int nb) {
    __shared__ int sh[128];
    int v = (threadIdx.x < nb) ? partials[threadIdx.x] : 0;
    sh[threadIdx.x] = v;
    __syncthreads();
#pragma unroll
    for (int off = 1; off < 128; off <<= 1) {
        int t = (threadIdx.x >= off) ? sh[threadIdx.x - off] : 0;
        __syncthreads();
        sh[threadIdx.x] += t;
        __syncthreads();
    }
    if (threadIdx.x < nb) partials[threadIdx.x] = sh[threadIdx.x] - v;  // excl
}

__global__ void scan3_kernel(int* __restrict__ out, const int* __restrict__ partials,
                             int n, int E) {
    int i = blockIdx.x * blockDim.x + threadIdx.x;
    if (i < n) out[i] += partials[i / SCAN_BLK];
    if (i == 0) out[n] = E;
}

__global__ void fill_kernel(const int* __restrict__ dst, const int* __restrict__ src,
                            const float* __restrict__ val,
                            const int* __restrict__ ptr, int* __restrict__ cursor,
                            int* __restrict__ col, float* __restrict__ cval, int E) {
    int i = blockIdx.x * blockDim.x + threadIdx.x;
    if (i >= E) return;
    int d = dst[i];
    int pos = ptr[d] + atomicAdd(&cursor[d], 1);
    col[pos] = src[i];
    cval[pos] = val[i];
}

// ================= dense GEMM: C[M,128] = A[M,384] @ W[384,128] ==============
__global__ void gemm_kernel(const float* __restrict__ A,
                            const float* __restrict__ W,
                            float* __restrict__ C, int M) {
    __shared__ float As[8][64];
    __shared__ float Ws[8][128];
    const int block_row = blockIdx.x * 64;
    const int tid  = threadIdx.x;
    const int tcol = tid & 31;
    const int trow = tid >> 5;

    float acc[8][4];
#pragma unroll
    for (int i = 0; i < 8; i++)
#pragma unroll
        for (int j = 0; j < 4; j++) acc[i][j] = 0.f;

    for (int k0 = 0; k0 < INDIM; k0 += 8) {
#pragma unroll
        for (int i = 0; i < 2; i++) {
            int idx = tid + i * 256;
            int r  = idx >> 3;
            int kk = idx & 7;
            int gr = block_row + r;
            As[kk][r] = (gr < M) ? A[(size_t)gr * INDIM + k0 + kk] : 0.f;
        }
#pragma unroll
        for (int i = 0; i < 4; i++) {
            int idx = tid + i * 256;
            int kk = idx >> 7;
            int c  = idx & 127;
            Ws[kk][c] = W[(size_t)(k0 + kk) * D + c];
        }
        __syncthreads();
#pragma unroll
        for (int kk = 0; kk < 8; kk++) {
            float b[4];
#pragma unroll
            for (int j = 0; j < 4; j++) b[j] = Ws[kk][tcol * 4 + j];
#pragma unroll
            for (int i = 0; i < 8; i++) {
                float a = As[kk][trow * 8 + i];
#pragma unroll
                for (int j = 0; j < 4; j++) acc[i][j] += a * b[j];
            }
        }
        __syncthreads();
    }
#pragma unroll
    for (int i = 0; i < 8; i++) {
        int gr = block_row + trow * 8 + i;
        if (gr < M) {
            float4 v = make_float4(acc[i][0], acc[i][1], acc[i][2], acc[i][3]);
            *reinterpret_cast<float4*>(C + (size_t)gr * D + tcol * 4) = v;
        }
    }
}

// ================= fused gather SpMM layer ====================================
// one warp per destination row (u rows then b rows). Accumulate in registers,
// single write to *_new, fold running-sum update (no atomics, no memset).
__device__ __forceinline__ void gather_row(const int* __restrict__ ptr,
                                           const int* __restrict__ col,
                                           const float* __restrict__ val,
                                           const float* __restrict__ x,
                                           int row, int lane, float4& acc) {
    int s = __ldg(ptr + row);
    int e = __ldg(ptr + row + 1);
    int base = s;
    // full 32-edge chunks
    for (; base + 32 <= e; base += 32) {
        int   c = __ldg(col + base + lane);
        float v = __ldg(val + base + lane);
#pragma unroll 8
        for (int j = 0; j < 32; j++) {
            int   cj = __shfl_sync(0xffffffffu, c, j);
            float vj = __shfl_sync(0xffffffffu, v, j);
            float4 xv = __ldg(reinterpret_cast<const float4*>(x + (size_t)cj * D) + lane);
            acc.x += vj * xv.x; acc.y += vj * xv.y;
            acc.z += vj * xv.z; acc.w += vj * xv.w;
        }
    }
    // tail
    if (base < e) {
        int m = e - base;
        int   c = 0; float v = 0.f;
        if (base + lane < e) { c = __ldg(col + base + lane); v = __ldg(val + base + lane); }
        for (int j = 0; j < m; j++) {
            int   cj = __shfl_sync(0xffffffffu, c, j);
            float vj = __shfl_sync(0xffffffffu, v, j);
            float4 xv = __ldg(reinterpret_cast<const float4*>(x + (size_t)cj * D) + lane);
            acc.x += vj * xv.x; acc.y += vj * xv.y;
            acc.z += vj * xv.z; acc.w += vj * xv.w;
        }
    }
}

__global__ void spmm_layer_kernel(const int* __restrict__ bu_ptr, const int* __restrict__ bu_col,
                                  const float* __restrict__ bu_val,
                                  const int* __restrict__ uu_ptr, const int* __restrict__ uu_col,
                                  const float* __restrict__ uu_val,
                                  const int* __restrict__ ub_ptr, const int* __restrict__ ub_col,
                                  const float* __restrict__ ub_val,
                                  const int* __restrict__ bb_ptr, const int* __restrict__ bb_col,
                                  const float* __restrict__ bb_val,
                                  const float* __restrict__ u_cur, const float* __restrict__ b_cur,
                                  float* __restrict__ u_new, float* __restrict__ b_new,
                                  float* __restrict__ uS, float* __restrict__ bS) {
    const int lane = threadIdx.x & 31;
    const int w = (blockIdx.x * blockDim.x + threadIdx.x) >> 5;
    float4 acc = make_float4(0.f, 0.f, 0.f, 0.f);
    if (w < NUSR) {
        const int row = w;
        gather_row(bu_ptr, bu_col, bu_val, b_cur, row, lane, acc);
        gather_row(uu_ptr, uu_col, uu_val, u_cur, row, lane, acc);
        float4* outp = reinterpret_cast<float4*>(u_new + (size_t)row * D) + lane;
        float4* sump = reinterpret_cast<float4*>(uS + (size_t)row * D) + lane;
        *outp = acc;
        float4 s = *sump;
        s.x += acc.x; s.y += acc.y; s.z += acc.z; s.w += acc.w;
        *sump = s;
    } else if (w < NUSR + NBIZ) {
        const int row = w - NUSR;
        gather_row(ub_ptr, ub_col, ub_val, u_cur, row, lane, acc);
        gather_row(bb_ptr, bb_col, bb_val, b_cur, row, lane, acc);
        float4* outp = reinterpret_cast<float4*>(b_new + (size_t)row * D) + lane;
        float4* sump = reinterpret_cast<float4*>(bS + (size_t)row * D) + lane;
        *outp = acc;
        float4 s = *sump;
        s.x += acc.x; s.y += acc.y; s.z += acc.z; s.w += acc.w;
        *sump = s;
    }
}

// ================= epilogue: out = l2norm(sum * inv) =========================
__global__ void l2norm_kernel(const float* __restrict__ s,
                              float* __restrict__ out, int nrows, float inv) {
    const int lane = threadIdx.x & 31;
    const int row  = (blockIdx.x * blockDim.x + threadIdx.x) >> 5;
    if (row >= nrows) return;
    float4 v = reinterpret_cast<const float4*>(s + (size_t)row * D)[lane];
    v.x *= inv; v.y *= inv; v.z *= inv; v.w *= inv;
    float ss = v.x * v.x + v.y * v.y + v.z * v.z + v.w * v.w;
#pragma unroll
    for (int o = 16; o; o >>= 1) ss += __shfl_xor_sync(0xffffffffu, ss, o);
    float nrm = sqrtf(ss);
    float sc = 1.0f / fmaxf(nrm, 1e-12f);
    v.x *= sc; v.y *= sc; v.z *= sc; v.w *= sc;
    reinterpret_cast<float4*>(out + (size_t)row * D)[lane] = v;
}

// ================= host-side CSR build helper =================================
static void build_csr(const int* dst, const int* src, const float* val,
                      int* ptr, int* col, float* cval, int* cnt, int* part,
                      int n_rows, int E) {
    cudaMemsetAsync(cnt, 0, n_rows * sizeof(int));
    hist_kernel<<<(E + 255) / 256, 256>>>(dst, cnt, E);
    int nb = (n_rows + SCAN_BLK - 1) / SCAN_BLK;
    scan1_kernel<<<nb, SCAN_BLK>>>(cnt, ptr, part, n_rows);
    scan2_kernel<<<1, 128>>>(part, nb);
    scan3_kernel<<<(n_rows + 255) / 256, 256>>>(ptr, part, n_rows, E);
    cudaMemsetAsync(cnt, 0, n_rows * sizeof(int));
    fill_kernel<<<(E + 255) / 256, 256>>>(dst, src, val, ptr, cnt, col, cval, E);
}

// ================= launcher ====================================================
extern "C" void kernel_launch(void* const* d_in, const int* in_sizes, int n_in,
                              void* d_out, int out_size) {
    const float* user_feat = (const float*)d_in[0];
    const float* biz_feat  = (const float*)d_in[1];
    const float* W_user    = (const float*)d_in[2];
    const float* W_biz     = (const float*)d_in[3];
    const int*   ub_u      = (const int*)  d_in[4];
    const int*   ub_b      = (const int*)  d_in[5];
    const float* val_ub    = (const float*)d_in[6];
    const float* val_bu    = (const float*)d_in[7];
    const int*   uu_src    = (const int*)  d_in[8];
    const int*   uu_dst    = (const int*)  d_in[9];
    const float* uu_val    = (const float*)d_in[10];
    const int*   bb_src    = (const int*)  d_in[11];
    const int*   bb_dst    = (const int*)  d_in[12];
    const float* bb_val    = (const float*)d_in[13];
    float* out = (float*)d_out;

    float *uA, *uB, *uS, *bA, *bB, *bS;
    cudaGetSymbolAddress((void**)&uA, g_uA);
    cudaGetSymbolAddress((void**)&uB, g_uB);
    cudaGetSymbolAddress((void**)&uS, g_uS);
    cudaGetSymbolAddress((void**)&bA, g_bA);
    cudaGetSymbolAddress((void**)&bB, g_bB);
    cudaGetSymbolAddress((void**)&bS, g_bS);

    int *bu_ptr, *bu_col, *uu_ptr, *uu_col, *ub_ptr, *ub_col, *bb_ptr, *bb_col;
    float *bu_valc, *uu_valc, *ub_valc, *bb_valc;
    int *cnt, *part;
    cudaGetSymbolAddress((void**)&bu_ptr, g_bu_ptr);
    cudaGetSymbolAddress((void**)&bu_col, g_bu_col);
    cudaGetSymbolAddress((void**)&bu_valc, g_bu_val);
    cudaGetSymbolAddress((void**)&uu_ptr, g_uu_ptr);
    cudaGetSymbolAddress((void**)&uu_col, g_uu_col);
    cudaGetSymbolAddress((void**)&uu_valc, g_uu_val);
    cudaGetSymbolAddress((void**)&ub_ptr, g_ub_ptr);
    cudaGetSymbolAddress((void**)&ub_col, g_ub_col);
    cudaGetSymbolAddress((void**)&ub_valc, g_ub_val);
    cudaGetSymbolAddress((void**)&bb_ptr, g_bb_ptr);
    cudaGetSymbolAddress((void**)&bb_col, g_bb_col);
    cudaGetSymbolAddress((void**)&bb_valc, g_bb_val);
    cudaGetSymbolAddress((void**)&cnt, g_cnt);
    cudaGetSymbolAddress((void**)&part, g_part);

    const size_t uBytes = (size_t)NUSR * D * sizeof(float);
    const size_t bBytes = (size_t)NBIZ * D * sizeof(float);

    // layer-0 embeddings
    gemm_kernel<<<(NUSR + 63) / 64, 256>>>(user_feat, W_user, uA, NUSR);
    gemm_kernel<<<(NBIZ + 63) / 64, 256>>>(biz_feat,  W_biz,  bA, NBIZ);

    // CSR builds (reused across 3 layers)
    build_csr(ub_u, ub_b, val_bu, bu_ptr, bu_col, bu_valc, cnt, part, NUSR, EUB);
    build_csr(uu_dst, uu_src, uu_val, uu_ptr, uu_col, uu_valc, cnt, part, NUSR, EUU);
    build_csr(ub_b, ub_u, val_ub, ub_ptr, ub_col, ub_valc, cnt, part, NBIZ, EUB);
    build_csr(bb_dst, bb_src, bb_val, bb_ptr, bb_col, bb_valc, cnt, part, NBIZ, EBB);

    // running sums start at layer-0 output
    cudaMemcpyAsync(uS, uA, uBytes, cudaMemcpyDeviceToDevice);
    cudaMemcpyAsync(bS, bA, bBytes, cudaMemcpyDeviceToDevice);

    float* u_cur = uA; float* u_new = uB;
    float* b_cur = bA; float* b_new = bB;

    const int totWarps = NUSR + NBIZ;
    const int spmmBlocks = (totWarps * 32 + 255) / 256;

    for (int layer = 0; layer < 3; layer++) {
        spmm_layer_kernel<<<spmmBlocks, 256>>>(
            bu_ptr, bu_col, bu_valc, uu_ptr, uu_col, uu_valc,
            ub_ptr, ub_col, ub_valc, bb_ptr, bb_col, bb_valc,
            u_cur, b_cur, u_new, b_new, uS, bS);
        float* t;
        t = u_cur; u_cur = u_new; u_new = t;
        t = b_cur; b_cur = b_new; b_new = t;
    }

    const float inv = 1.0f / 4.0f;
    l2norm_kernel<<<(NUSR * 32 + 255) / 256, 256>>>(uS, out, NUSR, inv);
    l2norm_kernel<<<(NBIZ * 32 + 255) / 256, 256>>>(bS, out + (size_t)NUSR * D,
                                                    NBIZ, inv);
    (void)n_in; (void)in_sizes; (void)out_size;
}

// round 5
// speedup vs baseline: 2.6595x; 1.2995x over previous
#include <cuda_runtime.h>
#include <cuda_fp16.h>
#include <mma.h>
#include <cstdint>

using namespace nvcuda;

#define NUSR 100000
#define NBIZ 20000
#define NUSR_PAD 100096
#define NBIZ_PAD 20096
#define EUB  3200000
#define EUU  1600000
#define EBB  320000
#define INDIM 384
#define D    128
#define DH   64

__device__ float g_uS[(size_t)NUSR_PAD * D];
__device__ float g_bS[(size_t)NBIZ_PAD * D];
__device__ __half2 g_uhA[(size_t)NUSR_PAD * DH];
__device__ __half2 g_uhB[(size_t)NUSR_PAD * DH];
__device__ __half2 g_bhA[(size_t)NBIZ_PAD * DH];
__device__ __half2 g_bhB[(size_t)NBIZ_PAD * DH];

__device__ int  g_bu_ptr[NUSR + 1];
__device__ int2 g_bu_cv[EUB];
__device__ int  g_uu_ptr[NUSR + 1];
__device__ int2 g_uu_cv[EUU];
__device__ int  g_ub_ptr[NBIZ + 1];
__device__ int2 g_ub_cv[EUB];
__device__ int  g_bb_ptr[NBIZ + 1];
__device__ int2 g_bb_cv[EBB];
__device__ int  g_cnt[NUSR];
__device__ int  g_part[128];

// ================= CSR build =================================================
__global__ void hist_kernel(const int* __restrict__ dst, int* __restrict__ cnt,
                            int E) {
    int i = blockIdx.x * blockDim.x + threadIdx.x;
    if (i < E) atomicAdd(&cnt[dst[i]], 1);
}

#define SCAN_BLK 1024
__global__ void scan1_kernel(const int* __restrict__ cnt, int* __restrict__ out,
                             int* __restrict__ partials, int n) {
    __shared__ int sh[SCAN_BLK];
    int i = blockIdx.x * SCAN_BLK + threadIdx.x;
    int v = (i < n) ? cnt[i] : 0;
    sh[threadIdx.x] = v;
    __syncthreads();
#pragma unroll
    for (int off = 1; off < SCAN_BLK; off <<= 1) {
        int t = (threadIdx.x >= off) ? sh[threadIdx.x - off] : 0;
        __syncthreads();
        sh[threadIdx.x] += t;
        __syncthreads();
    }
    if (i < n) out[i] = sh[threadIdx.x] - v;
    if (threadIdx.x == SCAN_BLK - 1) partials[blockIdx.x] = sh[threadIdx.x];
}

__global__ void scan2_kernel(int* __restrict__ partials, int nb) {
    __shared__ int sh[128];
    int v = (threadIdx.x < nb) ? partials[threadIdx.x] : 0;
    sh[threadIdx.x] = v;
    __syncthreads();
#pragma unroll
    for (int off = 1; off < 128; off <<= 1) {
        int t = (threadIdx.x >= off) ? sh[threadIdx.x - off] : 0;
        __syncthreads();
        sh[threadIdx.x] += t;
        __syncthreads();
    }
    if (threadIdx.x < nb) partials[threadIdx.x] = sh[threadIdx.x] - v;
}

__global__ void scan3_kernel(int* __restrict__ out, const int* __restrict__ partials,
                             int n, int E) {
    int i = blockIdx.x * blockDim.x + threadIdx.x;
    if (i < n) out[i] += partials[i / SCAN_BLK];
    if (i == 0) out[n] = E;
}

__global__ void fill_kernel(const int* __restrict__ dst, const int* __restrict__ src,
                            const float* __restrict__ val,
                            const int* __restrict__ ptr, int* __restrict__ cursor,
                            int2* __restrict__ cv, int E) {
    int i = blockIdx.x * blockDim.x + threadIdx.x;
    if (i >= E) return;
    int d = dst[i];
    int pos = ptr[d] + atomicAdd(&cursor[d], 1);
    cv[pos] = make_int2(src[i], __float_as_int(val[i]));
}

// ================= tensor-core GEMM: S[M,128] = A[M,384] @ W[384,128] ========
#define GBM 128
#define GBK 16
__global__ void gemm_tc_kernel(const float* __restrict__ A,
                               const float* __restrict__ W,
                               float* __restrict__ S, int M) {
    __shared__ __half Ash[GBM][GBK + 8];
    __shared__ __half Wsh[GBK][D + 8];
    const int tid  = threadIdx.x;
    const int warp = tid >> 5;
    const int wr   = warp >> 1;
    const int wc   = warp & 1;
    const int row0 = blockIdx.x * GBM;

    wmma::fragment<wmma::accumulator, 16, 16, 16, float> acc[2][4];
#pragma unroll
    for (int r = 0; r < 2; r++)
#pragma unroll
        for (int c = 0; c < 4; c++) wmma::fill_fragment(acc[r][c], 0.0f);

    for (int k0 = 0; k0 < INDIM; k0 += GBK) {
#pragma unroll
        for (int i = 0; i < 8; i++) {
            int idx = tid + i * 256;
            int r  = idx >> 4;
            int kk = idx & 15;
            int gr = row0 + r;
            float a = (gr < M) ? __ldg(A + (size_t)gr * INDIM + k0 + kk) : 0.f;
            Ash[r][kk] = __float2half_rn(a);
        }
#pragma unroll
        for (int i = 0; i < 8; i++) {
            int idx = tid + i * 256;
            int kk = idx >> 7;
            int c  = idx & 127;
            Wsh[kk][c] = __float2half_rn(__ldg(W + (size_t)(k0 + kk) * D + c));
        }
        __syncthreads();

        wmma::fragment<wmma::matrix_a, 16, 16, 16, __half, wmma::row_major> fa[2];
        wmma::fragment<wmma::matrix_b, 16, 16, 16, __half, wmma::row_major> fb[4];
#pragma unroll
        for (int r = 0; r < 2; r++)
            wmma::load_matrix_sync(fa[r], &Ash[wr * 32 + r * 16][0], GBK + 8);
#pragma unroll
        for (int c = 0; c < 4; c++)
            wmma::load_matrix_sync(fb[c], &Wsh[0][wc * 64 + c * 16], D + 8);
#pragma unroll
        for (int r = 0; r < 2; r++)
#pragma unroll
            for (int c = 0; c < 4; c++)
                wmma::mma_sync(acc[r][c], fa[r], fb[c], acc[r][c]);
        __syncthreads();
    }
#pragma unroll
    for (int r = 0; r < 2; r++)
#pragma unroll
        for (int c = 0; c < 4; c++)
            wmma::store_matrix_sync(
                S + (size_t)(row0 + wr * 32 + r * 16) * D + wc * 64 + c * 16,
                acc[r][c], D, wmma::mem_row_major);
}

__global__ void f2h_kernel(const float* __restrict__ S, __half2* __restrict__ H,
                           int n4) {
    int i = blockIdx.x * blockDim.x + threadIdx.x;
    if (i >= n4) return;
    float4 v = reinterpret_cast<const float4*>(S)[i];
    uint2 h;
    __half2 h0 = __float22half2_rn(make_float2(v.x, v.y));
    __half2 h1 = __float22half2_rn(make_float2(v.z, v.w));
    h.x = *reinterpret_cast<uint32_t*>(&h0);
    h.y = *reinterpret_cast<uint32_t*>(&h1);
    reinterpret_cast<uint2*>(H)[i] = h;
}

// ================= fused gather SpMM layer (fp16 source rows) ================
__device__ __forceinline__ void gather_row_h(const int* __restrict__ ptr,
                                             const int2* __restrict__ cv,
                                             const __half2* __restrict__ x,
                                             int row, int lane, float4& acc) {
    int s = __ldg(ptr + row);
    int e = __ldg(ptr + row + 1);
    for (int base = s; base < e; base += 32) {
        int idx = base + lane;
        int c = 0; float v = 0.f;
        if (idx < e) {
            int2 p = __ldg(cv + idx);
            c = p.x; v = __int_as_float(p.y);
        }
#pragma unroll 8
        for (int j = 0; j < 32; j++) {
            float vj = __shfl_sync(0xffffffffu, v, j);
            int   cj = __shfl_sync(0xffffffffu, c, j);
            if (vj != 0.0f) {
                uint2 raw = __ldg(reinterpret_cast<const uint2*>(x + (size_t)cj * DH) + lane);
                __half2 p0 = *reinterpret_cast<__half2*>(&raw.x);
                __half2 p1 = *reinterpret_cast<__half2*>(&raw.y);
                float2 f0 = __half22float2(p0);
                float2 f1 = __half22float2(p1);
                acc.x += vj * f0.x; acc.y += vj * f0.y;
                acc.z += vj * f1.x; acc.w += vj * f1.y;
            }
        }
    }
}

__global__ void spmm_layer_kernel(const int* __restrict__ bu_ptr, const int2* __restrict__ bu_cv,
                                  const int* __restrict__ uu_ptr, const int2* __restrict__ uu_cv,
                                  const int* __restrict__ ub_ptr, const int2* __restrict__ ub_cv,
                                  const int* __restrict__ bb_ptr, const int2* __restrict__ bb_cv,
                                  const __half2* __restrict__ u_cur,
                                  const __half2* __restrict__ b_cur,
                                  __half2* __restrict__ u_new,
                                  __half2* __restrict__ b_new,
                                  float* __restrict__ uS, float* __restrict__ bS,
                                  int write_new) {
    const int lane = threadIdx.x & 31;
    const int w = (blockIdx.x * blockDim.x + threadIdx.x) >> 5;
    float4 acc = make_float4(0.f, 0.f, 0.f, 0.f);
    if (w < NUSR) {
        const int row = w;
        gather_row_h(bu_ptr, bu_cv, b_cur, row, lane, acc);
        gather_row_h(uu_ptr, uu_cv, u_cur, row, lane, acc);
        float4* sump = reinterpret_cast<float4*>(uS + (size_t)row * D) + lane;
        float4 s = *sump;
        s.x += acc.x; s.y += acc.y; s.z += acc.z; s.w += acc.w;
        *sump = s;
        if (write_new) {
            uint2 h;
            __half2 h0 = __float22half2_rn(make_float2(acc.x, acc.y));
            __half2 h1 = __float22half2_rn(make_float2(acc.z, acc.w));
            h.x = *reinterpret_cast<uint32_t*>(&h0);
            h.y = *reinterpret_cast<uint32_t*>(&h1);
            *reinterpret_cast<uint2*>(u_new + (size_t)row * DH + lane * 2) = h;
        }
    } else if (w < NUSR + NBIZ) {
        const int row = w - NUSR;
        gather_row_h(ub_ptr, ub_cv, u_cur, row, lane, acc);
        gather_row_h(bb_ptr, bb_cv, b_cur, row, lane, acc);
        float4* sump = reinterpret_cast<float4*>(bS + (size_t)row * D) + lane;
        float4 s = *sump;
        s.x += acc.x; s.y += acc.y; s.z += acc.z; s.w += acc.w;
        *sump = s;
        if (write_new) {
            uint2 h;
            __half2 h0 = __float22half2_rn(make_float2(acc.x, acc.y));
            __half2 h1 = __float22half2_rn(make_float2(acc.z, acc.w));
            h.x = *reinterpret_cast<uint32_t*>(&h0);
            h.y = *reinterpret_cast<uint32_t*>(&h1);
            *reinterpret_cast<uint2*>(b_new + (size_t)row * DH + lane * 2) = h;
        }
    }
}

// ================= epilogue: out = l2norm(sum * inv) =========================
__global__ void l2norm_kernel(const float* __restrict__ s,
                              float* __restrict__ out, int nrows, float inv) {
    const int lane = threadIdx.x & 31;
    const int row  = (blockIdx.x * blockDim.x + threadIdx.x) >> 5;
    if (row >= nrows) return;
    float4 v = reinterpret_cast<const float4*>(s + (size_t)row * D)[lane];
    v.x *= inv; v.y *= inv; v.z *= inv; v.w *= inv;
    float ss = v.x * v.x + v.y * v.y + v.z * v.z + v.w * v.w;
#pragma unroll
    for (int o = 16; o; o >>= 1) ss += __shfl_xor_sync(0xffffffffu, ss, o);
    float nrm = sqrtf(ss);
    float sc = 1.0f / fmaxf(nrm, 1e-12f);
    v.x *= sc; v.y *= sc; v.z *= sc; v.w *= sc;
    reinterpret_cast<float4*>(out + (size_t)row * D)[lane] = v;
}

// ================= host-side CSR build helper =================================
static void build_csr(const int* dst, const int* src, const float* val,
                      int* ptr, int2* cv, int* cnt, int* part,
                      int n_rows, int E) {
    cudaMemsetAsync(cnt, 0, n_rows * sizeof(int));
    hist_kernel<<<(E + 255) / 256, 256>>>(dst, cnt, E);
    int nb = (n_rows + SCAN_BLK - 1) / SCAN_BLK;
    scan1_kernel<<<nb, SCAN_BLK>>>(cnt, ptr, part, n_rows);
    scan2_kernel<<<1, 128>>>(part, nb);
    scan3_kernel<<<(n_rows + 255) / 256, 256>>>(ptr, part, n_rows, E);
    cudaMemsetAsync(cnt, 0, n_rows * sizeof(int));
    fill_kernel<<<(E + 255) / 256, 256>>>(dst, src, val, ptr, cnt, cv, E);
}

// ================= launcher ====================================================
extern "C" void kernel_launch(void* const* d_in, const int* in_sizes, int n_in,
                              void* d_out, int out_size) {
    const float* user_feat = (const float*)d_in[0];
    const float* biz_feat  = (const float*)d_in[1];
    const float* W_user    = (const float*)d_in[2];
    const float* W_biz     = (const float*)d_in[3];
    const int*   ub_u      = (const int*)  d_in[4];
    const int*   ub_b      = (const int*)  d_in[5];
    const float* val_ub    = (const float*)d_in[6];
    const float* val_bu    = (const float*)d_in[7];
    const int*   uu_src    = (const int*)  d_in[8];
    const int*   uu_dst    = (const int*)  d_in[9];
    const float* uu_val    = (const float*)d_in[10];
    const int*   bb_src    = (const int*)  d_in[11];
    const int*   bb_dst    = (const int*)  d_in[12];
    const float* bb_val    = (const float*)d_in[13];
    float* out = (float*)d_out;

    float *uS, *bS;
    __half2 *uhA, *uhB, *bhA, *bhB;
    cudaGetSymbolAddress((void**)&uS, g_uS);
    cudaGetSymbolAddress((void**)&bS, g_bS);
    cudaGetSymbolAddress((void**)&uhA, g_uhA);
    cudaGetSymbolAddress((void**)&uhB, g_uhB);
    cudaGetSymbolAddress((void**)&bhA, g_bhA);
    cudaGetSymbolAddress((void**)&bhB, g_bhB);

    int *bu_ptr, *uu_ptr, *ub_ptr, *bb_ptr, *cnt, *part;
    int2 *bu_cv, *uu_cv, *ub_cv, *bb_cv;
    cudaGetSymbolAddress((void**)&bu_ptr, g_bu_ptr);
    cudaGetSymbolAddress((void**)&bu_cv,  g_bu_cv);
    cudaGetSymbolAddress((void**)&uu_ptr, g_uu_ptr);
    cudaGetSymbolAddress((void**)&uu_cv,  g_uu_cv);
    cudaGetSymbolAddress((void**)&ub_ptr, g_ub_ptr);
    cudaGetSymbolAddress((void**)&ub_cv,  g_ub_cv);
    cudaGetSymbolAddress((void**)&bb_ptr, g_bb_ptr);
    cudaGetSymbolAddress((void**)&bb_cv,  g_bb_cv);
    cudaGetSymbolAddress((void**)&cnt, g_cnt);
    cudaGetSymbolAddress((void**)&part, g_part);

    gemm_tc_kernel<<<NUSR_PAD / GBM, 256>>>(user_feat, W_user, uS, NUSR);
    gemm_tc_kernel<<<NBIZ_PAD / GBM, 256>>>(biz_feat,  W_biz,  bS, NBIZ);
    f2h_kernel<<<(NUSR_PAD * D / 4 + 255) / 256, 256>>>(uS, uhA, NUSR_PAD * D / 4);
    f2h_kernel<<<(NBIZ_PAD * D / 4 + 255) / 256, 256>>>(bS, bhA, NBIZ_PAD * D / 4);

    build_csr(ub_u,  ub_b,  val_bu, bu_ptr, bu_cv, cnt, part, NUSR, EUB);
    build_csr(uu_dst, uu_src, uu_val, uu_ptr, uu_cv, cnt, part, NUSR, EUU);
    build_csr(ub_b,  ub_u,  val_ub, ub_ptr, ub_cv, cnt, part, NBIZ, EUB);
    build_csr(bb_dst, bb_src, bb_val, bb_ptr, bb_cv, cnt, part, NBIZ, EBB);

    __half2* u_cur = uhA; __half2* u_new = uhB;
    __half2* b_cur = bhA; __half2* b_new = bhB;

    const int totWarps = NUSR + NBIZ;
    const int spmmBlocks = (totWarps * 32 + 255) / 256;

    for (int layer = 0; layer < 3; layer++) {
        spmm_layer_kernel<<<spmmBlocks, 256>>>(
            bu_ptr, bu_cv, uu_ptr, uu_cv, ub_ptr, ub_cv, bb_ptr, bb_cv,
            u_cur, b_cur, u_new, b_new, uS, bS, layer < 2 ? 1 : 0);
        __half2* t;
        t = u_cur; u_cur = u_new; u_new = t;
        t = b_cur; b_cur = b_new; b_new = t;
    }

    const float inv = 1.0f / 4.0f;
    l2norm_kernel<<<(NUSR * 32 + 255) / 256, 256>>>(uS, out, NUSR, inv);
    l2norm_kernel<<<(NBIZ * 32 + 255) / 256, 256>>>(bS, out + (size_t)NUSR * D,
                                                    NBIZ, inv);
    (void)n_in; (void)in_sizes; (void)out_size;
}

// round 6
// speedup vs baseline: 2.8454x; 1.0699x over previous
#include <cuda_runtime.h>
#include <cuda_fp16.h>
#include <mma.h>
#include <cstdint>

using namespace nvcuda;

#define NUSR 100000
#define NBIZ 20000
#define NUSR_PAD 100096
#define NBIZ_PAD 20096
#define EUB  3200000
#define EUU  1600000
#define EBB  320000
#define INDIM 384
#define D    128
#define DH   64

// padded CSR capacities (each row segment rounded up to multiple of 32)
#define CAP_BU (EUB + 32 * NUSR)
#define CAP_UU (EUU + 32 * NUSR)
#define CAP_UB (EUB + 32 * NBIZ)
#define CAP_BB (EBB + 32 * NBIZ)

__device__ float g_uS[(size_t)NUSR_PAD * D];
__device__ float g_bS[(size_t)NBIZ_PAD * D];
__device__ __half2 g_uhA[(size_t)NUSR_PAD * DH];
__device__ __half2 g_uhB[(size_t)NUSR_PAD * DH];
__device__ __half2 g_bhA[(size_t)NBIZ_PAD * DH];
__device__ __half2 g_bhB[(size_t)NBIZ_PAD * DH];

__device__ int  g_bu_ptr[NUSR + 1];
__device__ int2 g_bu_cv[CAP_BU];
__device__ int  g_uu_ptr[NUSR + 1];
__device__ int2 g_uu_cv[CAP_UU];
__device__ int  g_ub_ptr[NBIZ + 1];
__device__ int2 g_ub_cv[CAP_UB];
__device__ int  g_bb_ptr[NBIZ + 1];
__device__ int2 g_bb_cv[CAP_BB];
__device__ int  g_cnt[NUSR];
__device__ int  g_part[128];

// ================= CSR build =================================================
__global__ void hist_kernel(const int* __restrict__ dst, int* __restrict__ cnt,
                            int E) {
    int i = blockIdx.x * blockDim.x + threadIdx.x;
    if (i < E) atomicAdd(&cnt[dst[i]], 1);
}

// scan over PADDED counts: pad(c) = (c+31) & ~31  (0 stays 0)
#define SCAN_BLK 1024
__global__ void scan1_kernel(const int* __restrict__ cnt, int* __restrict__ out,
                             int* __restrict__ partials, int n) {
    __shared__ int sh[SCAN_BLK];
    int i = blockIdx.x * SCAN_BLK + threadIdx.x;
    int v = (i < n) ? ((cnt[i] + 31) & ~31) : 0;
    sh[threadIdx.x] = v;
    __syncthreads();
#pragma unroll
    for (int off = 1; off < SCAN_BLK; off <<= 1) {
        int t = (threadIdx.x >= off) ? sh[threadIdx.x - off] : 0;
        __syncthreads();
        sh[threadIdx.x] += t;
        __syncthreads();
    }
    if (i < n) out[i] = sh[threadIdx.x] - v;
    if (threadIdx.x == SCAN_BLK - 1) partials[blockIdx.x] = sh[threadIdx.x];
}

__global__ void scan2_kernel(int* __restrict__ partials, int nb) {
    __shared__ int sh[128];
    int v = (threadIdx.x < nb) ? partials[threadIdx.x] : 0;
    sh[threadIdx.x] = v;
    __syncthreads();
#pragma unroll
    for (int off = 1; off < 128; off <<= 1) {
        int t = (threadIdx.x >= off) ? sh[threadIdx.x - off] : 0;
        __syncthreads();
        sh[threadIdx.x] += t;
        __syncthreads();
    }
    if (threadIdx.x < nb) partials[threadIdx.x] = sh[threadIdx.x] - v;
}

__global__ void scan3_kernel(int* __restrict__ out, const int* __restrict__ partials,
                             const int* __restrict__ cnt, int n) {
    int i = blockIdx.x * blockDim.x + threadIdx.x;
    if (i < n) {
        int o = out[i] + partials[i / SCAN_BLK];
        out[i] = o;
        if (i == n - 1) out[n] = o + ((cnt[i] + 31) & ~31);
    }
}

__global__ void fill_kernel(const int* __restrict__ dst, const int* __restrict__ src,
                            const float* __restrict__ val,
                            const int* __restrict__ ptr, int* __restrict__ cursor,
                            int2* __restrict__ cv, int E) {
    int i = blockIdx.x * blockDim.x + threadIdx.x;
    if (i >= E) return;
    int d = dst[i];
    int pos = ptr[d] + atomicAdd(&cursor[d], 1);
    cv[pos] = make_int2(src[i], __float_as_int(val[i]));
}

// ================= tensor-core GEMM: S[M,128] = A[M,384] @ W[384,128] ========
#define GBM 128
#define GBK 16
__global__ void gemm_tc_kernel(const float* __restrict__ A,
                               const float* __restrict__ W,
                               float* __restrict__ S, int M) {
    __shared__ __half Ash[GBM][GBK + 8];
    __shared__ __half Wsh[GBK][D + 8];
    const int tid  = threadIdx.x;
    const int warp = tid >> 5;
    const int wr   = warp >> 1;
    const int wc   = warp & 1;
    const int row0 = blockIdx.x * GBM;

    wmma::fragment<wmma::accumulator, 16, 16, 16, float> acc[2][4];
#pragma unroll
    for (int r = 0; r < 2; r++)
#pragma unroll
        for (int c = 0; c < 4; c++) wmma::fill_fragment(acc[r][c], 0.0f);

    for (int k0 = 0; k0 < INDIM; k0 += GBK) {
#pragma unroll
        for (int i = 0; i < 8; i++) {
            int idx = tid + i * 256;
            int r  = idx >> 4;
            int kk = idx & 15;
            int gr = row0 + r;
            float a = (gr < M) ? __ldg(A + (size_t)gr * INDIM + k0 + kk) : 0.f;
            Ash[r][kk] = __float2half_rn(a);
        }
#pragma unroll
        for (int i = 0; i < 8; i++) {
            int idx = tid + i * 256;
            int kk = idx >> 7;
            int c  = idx & 127;
            Wsh[kk][c] = __float2half_rn(__ldg(W + (size_t)(k0 + kk) * D + c));
        }
        __syncthreads();

        wmma::fragment<wmma::matrix_a, 16, 16, 16, __half, wmma::row_major> fa[2];
        wmma::fragment<wmma::matrix_b, 16, 16, 16, __half, wmma::row_major> fb[4];
#pragma unroll
        for (int r = 0; r < 2; r++)
            wmma::load_matrix_sync(fa[r], &Ash[wr * 32 + r * 16][0], GBK + 8);
#pragma unroll
        for (int c = 0; c < 4; c++)
            wmma::load_matrix_sync(fb[c], &Wsh[0][wc * 64 + c * 16], D + 8);
#pragma unroll
        for (int r = 0; r < 2; r++)
#pragma unroll
            for (int c = 0; c < 4; c++)
                wmma::mma_sync(acc[r][c], fa[r], fb[c], acc[r][c]);
        __syncthreads();
    }
#pragma unroll
    for (int r = 0; r < 2; r++)
#pragma unroll
        for (int c = 0; c < 4; c++)
            wmma::store_matrix_sync(
                S + (size_t)(row0 + wr * 32 + r * 16) * D + wc * 64 + c * 16,
                acc[r][c], D, wmma::mem_row_major);
}

__global__ void f2h_kernel(const float* __restrict__ S, __half2* __restrict__ H,
                           int n4) {
    int i = blockIdx.x * blockDim.x + threadIdx.x;
    if (i >= n4) return;
    float4 v = reinterpret_cast<const float4*>(S)[i];
    uint2 h;
    __half2 h0 = __float22half2_rn(make_float2(v.x, v.y));
    __half2 h1 = __float22half2_rn(make_float2(v.z, v.w));
    h.x = *reinterpret_cast<uint32_t*>(&h0);
    h.y = *reinterpret_cast<uint32_t*>(&h1);
    reinterpret_cast<uint2*>(H)[i] = h;
}

// ================= fused gather SpMM layer (fp16 rows, padded CSR) ===========
// every row segment is a multiple of 32 edges (dummies have val=0, col=0):
// single unguarded fully-unrolled loop -> max load batching (MLP ~8).
__device__ __forceinline__ void gather_row_h(const int* __restrict__ ptr,
                                             const int2* __restrict__ cv,
                                             const __half2* __restrict__ x,
                                             int row, int lane, float4& acc) {
    int s = __ldg(ptr + row);
    int e = __ldg(ptr + row + 1);
    for (int base = s; base < e; base += 32) {
        int2 p = __ldg(cv + base + lane);
        int   c = p.x;
        float v = __int_as_float(p.y);
#pragma unroll 8
        for (int j = 0; j < 32; j++) {
            int   cj = __shfl_sync(0xffffffffu, c, j);
            float vj = __shfl_sync(0xffffffffu, v, j);
            uint2 raw = __ldg(reinterpret_cast<const uint2*>(x + (size_t)cj * DH) + lane);
            __half2 p0 = *reinterpret_cast<__half2*>(&raw.x);
            __half2 p1 = *reinterpret_cast<__half2*>(&raw.y);
            float2 f0 = __half22float2(p0);
            float2 f1 = __half22float2(p1);
            acc.x += vj * f0.x; acc.y += vj * f0.y;
            acc.z += vj * f1.x; acc.w += vj * f1.y;
        }
    }
}

__global__ void spmm_layer_kernel(const int* __restrict__ bu_ptr, const int2* __restrict__ bu_cv,
                                  const int* __restrict__ uu_ptr, const int2* __restrict__ uu_cv,
                                  const int* __restrict__ ub_ptr, const int2* __restrict__ ub_cv,
                                  const int* __restrict__ bb_ptr, const int2* __restrict__ bb_cv,
                                  const __half2* __restrict__ u_cur,
                                  const __half2* __restrict__ b_cur,
                                  __half2* __restrict__ u_new,
                                  __half2* __restrict__ b_new,
                                  float* __restrict__ uS, float* __restrict__ bS,
                                  int write_new) {
    const int lane = threadIdx.x & 31;
    const int w = (blockIdx.x * blockDim.x + threadIdx.x) >> 5;
    float4 acc = make_float4(0.f, 0.f, 0.f, 0.f);
    if (w < NUSR) {
        const int row = w;
        gather_row_h(bu_ptr, bu_cv, b_cur, row, lane, acc);
        gather_row_h(uu_ptr, uu_cv, u_cur, row, lane, acc);
        float4* sump = reinterpret_cast<float4*>(uS + (size_t)row * D) + lane;
        float4 s = *sump;
        s.x += acc.x; s.y += acc.y; s.z += acc.z; s.w += acc.w;
        *sump = s;
        if (write_new) {
            uint2 h;
            __half2 h0 = __float22half2_rn(make_float2(acc.x, acc.y));
            __half2 h1 = __float22half2_rn(make_float2(acc.z, acc.w));
            h.x = *reinterpret_cast<uint32_t*>(&h0);
            h.y = *reinterpret_cast<uint32_t*>(&h1);
            *reinterpret_cast<uint2*>(u_new + (size_t)row * DH + lane * 2) = h;
        }
    } else if (w < NUSR + NBIZ) {
        const int row = w - NUSR;
        gather_row_h(ub_ptr, ub_cv, u_cur, row, lane, acc);
        gather_row_h(bb_ptr, bb_cv, b_cur, row, lane, acc);
        float4* sump = reinterpret_cast<float4*>(bS + (size_t)row * D) + lane;
        float4 s = *sump;
        s.x += acc.x; s.y += acc.y; s.z += acc.z; s.w += acc.w;
        *sump = s;
        if (write_new) {
            uint2 h;
            __half2 h0 = __float22half2_rn(make_float2(acc.x, acc.y));
            __half2 h1 = __float22half2_rn(make_float2(acc.z, acc.w));
            h.x = *reinterpret_cast<uint32_t*>(&h0);
            h.y = *reinterpret_cast<uint32_t*>(&h1);
            *reinterpret_cast<uint2*>(b_new + (size_t)row * DH + lane * 2) = h;
        }
    }
}

// ================= epilogue: out = l2norm(sum * inv) =========================
__global__ void l2norm_kernel(const float* __restrict__ s,
                              float* __restrict__ out, int nrows, float inv) {
    const int lane = threadIdx.x & 31;
    const int row  = (blockIdx.x * blockDim.x + threadIdx.x) >> 5;
    if (row >= nrows) return;
    float4 v = reinterpret_cast<const float4*>(s + (size_t)row * D)[lane];
    v.x *= inv; v.y *= inv; v.z *= inv; v.w *= inv;
    float ss = v.x * v.x + v.y * v.y + v.z * v.z + v.w * v.w;
#pragma unroll
    for (int o = 16; o; o >>= 1) ss += __shfl_xor_sync(0xffffffffu, ss, o);
    float nrm = sqrtf(ss);
    float sc = 1.0f / fmaxf(nrm, 1e-12f);
    v.x *= sc; v.y *= sc; v.z *= sc; v.w *= sc;
    reinterpret_cast<float4*>(out + (size_t)row * D)[lane] = v;
}

// ================= host-side CSR build helper =================================
static void build_csr(const int* dst, const int* src, const float* val,
                      int* ptr, int2* cv, size_t cap, int* cnt, int* part,
                      int n_rows, int E) {
    cudaMemsetAsync(cnt, 0, n_rows * sizeof(int));
    cudaMemsetAsync(cv, 0, cap * sizeof(int2));   // dummy edges: col=0, val=0
    hist_kernel<<<(E + 255) / 256, 256>>>(dst, cnt, E);
    int nb = (n_rows + SCAN_BLK - 1) / SCAN_BLK;
    scan1_kernel<<<nb, SCAN_BLK>>>(cnt, ptr, part, n_rows);
    scan2_kernel<<<1, 128>>>(part, nb);
    scan3_kernel<<<(n_rows + 255) / 256, 256>>>(ptr, part, cnt, n_rows);
    cudaMemsetAsync(cnt, 0, n_rows * sizeof(int));
    fill_kernel<<<(E + 255) / 256, 256>>>(dst, src, val, ptr, cnt, cv, E);
}

// ================= launcher ====================================================
extern "C" void kernel_launch(void* const* d_in, const int* in_sizes, int n_in,
                              void* d_out, int out_size) {
    const float* user_feat = (const float*)d_in[0];
    const float* biz_feat  = (const float*)d_in[1];
    const float* W_user    = (const float*)d_in[2];
    const float* W_biz     = (const float*)d_in[3];
    const int*   ub_u      = (const int*)  d_in[4];
    const int*   ub_b      = (const int*)  d_in[5];
    const float* val_ub    = (const float*)d_in[6];
    const float* val_bu    = (const float*)d_in[7];
    const int*   uu_src    = (const int*)  d_in[8];
    const int*   uu_dst    = (const int*)  d_in[9];
    const float* uu_val    = (const float*)d_in[10];
    const int*   bb_src    = (const int*)  d_in[11];
    const int*   bb_dst    = (const int*)  d_in[12];
    const float* bb_val    = (const float*)d_in[13];
    float* out = (float*)d_out;

    float *uS, *bS;
    __half2 *uhA, *uhB, *bhA, *bhB;
    cudaGetSymbolAddress((void**)&uS, g_uS);
    cudaGetSymbolAddress((void**)&bS, g_bS);
    cudaGetSymbolAddress((void**)&uhA, g_uhA);
    cudaGetSymbolAddress((void**)&uhB, g_uhB);
    cudaGetSymbolAddress((void**)&bhA, g_bhA);
    cudaGetSymbolAddress((void**)&bhB, g_bhB);

    int *bu_ptr, *uu_ptr, *ub_ptr, *bb_ptr, *cnt, *part;
    int2 *bu_cv, *uu_cv, *ub_cv, *bb_cv;
    cudaGetSymbolAddress((void**)&bu_ptr, g_bu_ptr);
    cudaGetSymbolAddress((void**)&bu_cv,  g_bu_cv);
    cudaGetSymbolAddress((void**)&uu_ptr, g_uu_ptr);
    cudaGetSymbolAddress((void**)&uu_cv,  g_uu_cv);
    cudaGetSymbolAddress((void**)&ub_ptr, g_ub_ptr);
    cudaGetSymbolAddress((void**)&ub_cv,  g_ub_cv);
    cudaGetSymbolAddress((void**)&bb_ptr, g_bb_ptr);
    cudaGetSymbolAddress((void**)&bb_cv,  g_bb_cv);
    cudaGetSymbolAddress((void**)&cnt, g_cnt);
    cudaGetSymbolAddress((void**)&part, g_part);

    gemm_tc_kernel<<<NUSR_PAD / GBM, 256>>>(user_feat, W_user, uS, NUSR);
    gemm_tc_kernel<<<NBIZ_PAD / GBM, 256>>>(biz_feat,  W_biz,  bS, NBIZ);
    f2h_kernel<<<(NUSR_PAD * D / 4 + 255) / 256, 256>>>(uS, uhA, NUSR_PAD * D / 4);
    f2h_kernel<<<(NBIZ_PAD * D / 4 + 255) / 256, 256>>>(bS, bhA, NBIZ_PAD * D / 4);

    build_csr(ub_u,  ub_b,  val_bu, bu_ptr, bu_cv, CAP_BU, cnt, part, NUSR, EUB);
    build_csr(uu_dst, uu_src, uu_val, uu_ptr, uu_cv, CAP_UU, cnt, part, NUSR, EUU);
    build_csr(ub_b,  ub_u,  val_ub, ub_ptr, ub_cv, CAP_UB, cnt, part, NBIZ, EUB);
    build_csr(bb_dst, bb_src, bb_val, bb_ptr, bb_cv, CAP_BB, cnt, part, NBIZ, EBB);

    __half2* u_cur = uhA; __half2* u_new = uhB;
    __half2* b_cur = bhA; __half2* b_new = bhB;

    const int totWarps = NUSR + NBIZ;
    const int spmmBlocks = (totWarps * 32 + 255) / 256;

    for (int layer = 0; layer < 3; layer++) {
        spmm_layer_kernel<<<spmmBlocks, 256>>>(
            bu_ptr, bu_cv, uu_ptr, uu_cv, ub_ptr, ub_cv, bb_ptr, bb_cv,
            u_cur, b_cur, u_new, b_new, uS, bS, layer < 2 ? 1 : 0);
        __half2* t;
        t = u_cur; u_cur = u_new; u_new = t;
        t = b_cur; b_cur = b_new; b_new = t;
    }

    const float inv = 1.0f / 4.0f;
    l2norm_kernel<<<(NUSR * 32 + 255) / 256, 256>>>(uS, out, NUSR, inv);
    l2norm_kernel<<<(NBIZ * 32 + 255) / 256, 256>>>(bS, out + (size_t)NUSR * D,
                                                    NBIZ, inv);
    (void)n_in; (void)in_sizes; (void)out_size;
}

// round 7
// speedup vs baseline: 3.1869x; 1.1200x over previous
#include <cuda_runtime.h>
#include <cuda_fp16.h>
#include <mma.h>
#include <cstdint>

using namespace nvcuda;

#define NUSR 100000
#define NBIZ 20000
#define NUSR_PAD 100096
#define NBIZ_PAD 20096
#define EUB  3200000
#define EUU  1600000
#define EBB  320000
#define INDIM 384
#define D    128
#define DH   64

__device__ float g_uS[(size_t)NUSR_PAD * D];
__device__ float g_bS[(size_t)NBIZ_PAD * D];
__device__ __half2 g_uhA[(size_t)NUSR_PAD * DH];
__device__ __half2 g_uhB[(size_t)NUSR_PAD * DH];
__device__ __half2 g_bhA[(size_t)NBIZ_PAD * DH];
__device__ __half2 g_bhB[(size_t)NBIZ_PAD * DH];

__device__ int  g_bu_ptr[NUSR + 1];
__device__ int2 g_bu_cv[EUB];
__device__ int  g_uu_ptr[NUSR + 1];
__device__ int2 g_uu_cv[EUU];
__device__ int  g_ub_ptr[NBIZ + 1];
__device__ int2 g_ub_cv[EUB];
__device__ int  g_bb_ptr[NBIZ + 1];
__device__ int2 g_bb_cv[EBB];
__device__ int  g_cnt[NUSR];
__device__ int  g_part[128];

// ================= CSR build (unpadded) ======================================
__global__ void hist_kernel(const int* __restrict__ dst, int* __restrict__ cnt,
                            int E) {
    int i = blockIdx.x * blockDim.x + threadIdx.x;
    if (i < E) atomicAdd(&cnt[dst[i]], 1);
}

#define SCAN_BLK 1024
__global__ void scan1_kernel(const int* __restrict__ cnt, int* __restrict__ out,
                             int* __restrict__ partials, int n) {
    __shared__ int sh[SCAN_BLK];
    int i = blockIdx.x * SCAN_BLK + threadIdx.x;
    int v = (i < n) ? cnt[i] : 0;
    sh[threadIdx.x] = v;
    __syncthreads();
#pragma unroll
    for (int off = 1; off < SCAN_BLK; off <<= 1) {
        int t = (threadIdx.x >= off) ? sh[threadIdx.x - off] : 0;
        __syncthreads();
        sh[threadIdx.x] += t;
        __syncthreads();
    }
    if (i < n) out[i] = sh[threadIdx.x] - v;
    if (threadIdx.x == SCAN_BLK - 1) partials[blockIdx.x] = sh[threadIdx.x];
}

__global__ void scan2_kernel(int* __restrict__ partials, int nb) {
    __shared__ int sh[128];
    int v = (threadIdx.x < nb) ? partials[threadIdx.x] : 0;
    sh[threadIdx.x] = v;
    __syncthreads();
#pragma unroll
    for (int off = 1; off < 128; off <<= 1) {
        int t = (threadIdx.x >= off) ? sh[threadIdx.x - off] : 0;
        __syncthreads();
        sh[threadIdx.x] += t;
        __syncthreads();
    }
    if (threadIdx.x < nb) partials[threadIdx.x] = sh[threadIdx.x] - v;
}

__global__ void scan3_kernel(int* __restrict__ out, const int* __restrict__ partials,
                             int n, int E) {
    int i = blockIdx.x * blockDim.x + threadIdx.x;
    if (i < n) out[i] += partials[i / SCAN_BLK];
    if (i == 0) out[n] = E;
}

__global__ void fill_kernel(const int* __restrict__ dst, const int* __restrict__ src,
                            const float* __restrict__ val,
                            const int* __restrict__ ptr, int* __restrict__ cursor,
                            int2* __restrict__ cv, int E) {
    int i = blockIdx.x * blockDim.x + threadIdx.x;
    if (i >= E) return;
    int d = dst[i];
    int pos = ptr[d] + atomicAdd(&cursor[d], 1);
    cv[pos] = make_int2(src[i], __float_as_int(val[i]));
}

// ================= tensor-core GEMM: S[M,128] = A[M,384] @ W[384,128] ========
#define GBM 128
#define GBK 16
__global__ void gemm_tc_kernel(const float* __restrict__ A,
                               const float* __restrict__ W,
                               float* __restrict__ S, int M) {
    __shared__ __half Ash[GBM][GBK + 8];
    __shared__ __half Wsh[GBK][D + 8];
    const int tid  = threadIdx.x;
    const int warp = tid >> 5;
    const int wr   = warp >> 1;
    const int wc   = warp & 1;
    const int row0 = blockIdx.x * GBM;

    wmma::fragment<wmma::accumulator, 16, 16, 16, float> acc[2][4];
#pragma unroll
    for (int r = 0; r < 2; r++)
#pragma unroll
        for (int c = 0; c < 4; c++) wmma::fill_fragment(acc[r][c], 0.0f);

    for (int k0 = 0; k0 < INDIM; k0 += GBK) {
#pragma unroll
        for (int i = 0; i < 8; i++) {
            int idx = tid + i * 256;
            int r  = idx >> 4;
            int kk = idx & 15;
            int gr = row0 + r;
            float a = (gr < M) ? __ldg(A + (size_t)gr * INDIM + k0 + kk) : 0.f;
            Ash[r][kk] = __float2half_rn(a);
        }
#pragma unroll
        for (int i = 0; i < 8; i++) {
            int idx = tid + i * 256;
            int kk = idx >> 7;
            int c  = idx & 127;
            Wsh[kk][c] = __float2half_rn(__ldg(W + (size_t)(k0 + kk) * D + c));
        }
        __syncthreads();

        wmma::fragment<wmma::matrix_a, 16, 16, 16, __half, wmma::row_major> fa[2];
        wmma::fragment<wmma::matrix_b, 16, 16, 16, __half, wmma::row_major> fb[4];
#pragma unroll
        for (int r = 0; r < 2; r++)
            wmma::load_matrix_sync(fa[r], &Ash[wr * 32 + r * 16][0], GBK + 8);
#pragma unroll
        for (int c = 0; c < 4; c++)
            wmma::load_matrix_sync(fb[c], &Wsh[0][wc * 64 + c * 16], D + 8);
#pragma unroll
        for (int r = 0; r < 2; r++)
#pragma unroll
            for (int c = 0; c < 4; c++)
                wmma::mma_sync(acc[r][c], fa[r], fb[c], acc[r][c]);
        __syncthreads();
    }
#pragma unroll
    for (int r = 0; r < 2; r++)
#pragma unroll
        for (int c = 0; c < 4; c++)
            wmma::store_matrix_sync(
                S + (size_t)(row0 + wr * 32 + r * 16) * D + wc * 64 + c * 16,
                acc[r][c], D, wmma::mem_row_major);
}

__global__ void f2h_kernel(const float* __restrict__ S, __half2* __restrict__ H,
                           int n4) {
    int i = blockIdx.x * blockDim.x + threadIdx.x;
    if (i >= n4) return;
    float4 v = reinterpret_cast<const float4*>(S)[i];
    uint2 h;
    __half2 h0 = __float22half2_rn(make_float2(v.x, v.y));
    __half2 h1 = __float22half2_rn(make_float2(v.z, v.w));
    h.x = *reinterpret_cast<uint32_t*>(&h0);
    h.y = *reinterpret_cast<uint32_t*>(&h1);
    reinterpret_cast<uint2*>(H)[i] = h;
}

// ================= fused gather SpMM layer (fp16 source rows) ================
// 32-edge chunks processed as 4 unrolled sub-blocks of 8 with warp-uniform
// early exit: loads batch 8-deep, dummy work only rounds each row to mult-of-8.
__device__ __forceinline__ void gather_row_h(const int* __restrict__ ptr,
                                             const int2* __restrict__ cv,
                                             const __half2* __restrict__ x,
                                             int row, int lane, float4& acc) {
    int s = __ldg(ptr + row);
    int e = __ldg(ptr + row + 1);
    for (int base = s; base < e; base += 32) {
        int rem = e - base;   // > 0, warp-uniform
        int c = 0; float v = 0.f;
        if (lane < rem) {
            int2 p = __ldg(cv + base + lane);
            c = p.x; v = __int_as_float(p.y);
        }
#pragma unroll
        for (int jb = 0; jb < 32; jb += 8) {
            if (jb >= rem) break;   // warp-uniform
#pragma unroll
            for (int jj = 0; jj < 8; jj++) {
                int   cj = __shfl_sync(0xffffffffu, c, jb + jj);
                float vj = __shfl_sync(0xffffffffu, v, jb + jj);
                uint2 raw = __ldg(reinterpret_cast<const uint2*>(x + (size_t)cj * DH) + lane);
                __half2 p0 = *reinterpret_cast<__half2*>(&raw.x);
                __half2 p1 = *reinterpret_cast<__half2*>(&raw.y);
                float2 f0 = __half22float2(p0);
                float2 f1 = __half22float2(p1);
                acc.x += vj * f0.x; acc.y += vj * f0.y;
                acc.z += vj * f1.x; acc.w += vj * f1.y;
            }
        }
    }
}

__global__ void spmm_layer_kernel(const int* __restrict__ bu_ptr, const int2* __restrict__ bu_cv,
                                  const int* __restrict__ uu_ptr, const int2* __restrict__ uu_cv,
                                  const int* __restrict__ ub_ptr, const int2* __restrict__ ub_cv,
                                  const int* __restrict__ bb_ptr, const int2* __restrict__ bb_cv,
                                  const __half2* __restrict__ u_cur,
                                  const __half2* __restrict__ b_cur,
                                  __half2* __restrict__ u_new,
                                  __half2* __restrict__ b_new,
                                  float* __restrict__ uS, float* __restrict__ bS,
                                  int write_new) {
    const int lane = threadIdx.x & 31;
    const int w = (blockIdx.x * blockDim.x + threadIdx.x) >> 5;
    float4 acc = make_float4(0.f, 0.f, 0.f, 0.f);
    if (w < NUSR) {
        const int row = w;
        gather_row_h(bu_ptr, bu_cv, b_cur, row, lane, acc);
        gather_row_h(uu_ptr, uu_cv, u_cur, row, lane, acc);
        float4* sump = reinterpret_cast<float4*>(uS + (size_t)row * D) + lane;
        float4 s = *sump;
        s.x += acc.x; s.y += acc.y; s.z += acc.z; s.w += acc.w;
        *sump = s;
        if (write_new) {
            uint2 h;
            __half2 h0 = __float22half2_rn(make_float2(acc.x, acc.y));
            __half2 h1 = __float22half2_rn(make_float2(acc.z, acc.w));
            h.x = *reinterpret_cast<uint32_t*>(&h0);
            h.y = *reinterpret_cast<uint32_t*>(&h1);
            *reinterpret_cast<uint2*>(u_new + (size_t)row * DH + lane * 2) = h;
        }
    } else if (w < NUSR + NBIZ) {
        const int row = w - NUSR;
        gather_row_h(ub_ptr, ub_cv, u_cur, row, lane, acc);
        gather_row_h(bb_ptr, bb_cv, b_cur, row, lane, acc);
        float4* sump = reinterpret_cast<float4*>(bS + (size_t)row * D) + lane;
        float4 s = *sump;
        s.x += acc.x; s.y += acc.y; s.z += acc.z; s.w += acc.w;
        *sump = s;
        if (write_new) {
            uint2 h;
            __half2 h0 = __float22half2_rn(make_float2(acc.x, acc.y));
            __half2 h1 = __float22half2_rn(make_float2(acc.z, acc.w));
            h.x = *reinterpret_cast<uint32_t*>(&h0);
            h.y = *reinterpret_cast<uint32_t*>(&h1);
            *reinterpret_cast<uint2*>(b_new + (size_t)row * DH + lane * 2) = h;
        }
    }
}

// ================= epilogue: out = l2norm(sum * inv) =========================
__global__ void l2norm_kernel(const float* __restrict__ s,
                              float* __restrict__ out, int nrows, float inv) {
    const int lane = threadIdx.x & 31;
    const int row  = (blockIdx.x * blockDim.x + threadIdx.x) >> 5;
    if (row >= nrows) return;
    float4 v = reinterpret_cast<const float4*>(s + (size_t)row * D)[lane];
    v.x *= inv; v.y *= inv; v.z *= inv; v.w *= inv;
    float ss = v.x * v.x + v.y * v.y + v.z * v.z + v.w * v.w;
#pragma unroll
    for (int o = 16; o; o >>= 1) ss += __shfl_xor_sync(0xffffffffu, ss, o);
    float nrm = sqrtf(ss);
    float sc = 1.0f / fmaxf(nrm, 1e-12f);
    v.x *= sc; v.y *= sc; v.z *= sc; v.w *= sc;
    reinterpret_cast<float4*>(out + (size_t)row * D)[lane] = v;
}

// ================= host-side CSR build helper =================================
static void build_csr(const int* dst, const int* src, const float* val,
                      int* ptr, int2* cv, int* cnt, int* part,
                      int n_rows, int E) {
    cudaMemsetAsync(cnt, 0, n_rows * sizeof(int));
    hist_kernel<<<(E + 255) / 256, 256>>>(dst, cnt, E);
    int nb = (n_rows + SCAN_BLK - 1) / SCAN_BLK;
    scan1_kernel<<<nb, SCAN_BLK>>>(cnt, ptr, part, n_rows);
    scan2_kernel<<<1, 128>>>(part, nb);
    scan3_kernel<<<(n_rows + 255) / 256, 256>>>(ptr, part, n_rows, E);
    cudaMemsetAsync(cnt, 0, n_rows * sizeof(int));
    fill_kernel<<<(E + 255) / 256, 256>>>(dst, src, val, ptr, cnt, cv, E);
}

// ================= launcher ====================================================
extern "C" void kernel_launch(void* const* d_in, const int* in_sizes, int n_in,
                              void* d_out, int out_size) {
    const float* user_feat = (const float*)d_in[0];
    const float* biz_feat  = (const float*)d_in[1];
    const float* W_user    = (const float*)d_in[2];
    const float* W_biz     = (const float*)d_in[3];
    const int*   ub_u      = (const int*)  d_in[4];
    const int*   ub_b      = (const int*)  d_in[5];
    const float* val_ub    = (const float*)d_in[6];
    const float* val_bu    = (const float*)d_in[7];
    const int*   uu_src    = (const int*)  d_in[8];
    const int*   uu_dst    = (const int*)  d_in[9];
    const float* uu_val    = (const float*)d_in[10];
    const int*   bb_src    = (const int*)  d_in[11];
    const int*   bb_dst    = (const int*)  d_in[12];
    const float* bb_val    = (const float*)d_in[13];
    float* out = (float*)d_out;

    float *uS, *bS;
    __half2 *uhA, *uhB, *bhA, *bhB;
    cudaGetSymbolAddress((void**)&uS, g_uS);
    cudaGetSymbolAddress((void**)&bS, g_bS);
    cudaGetSymbolAddress((void**)&uhA, g_uhA);
    cudaGetSymbolAddress((void**)&uhB, g_uhB);
    cudaGetSymbolAddress((void**)&bhA, g_bhA);
    cudaGetSymbolAddress((void**)&bhB, g_bhB);

    int *bu_ptr, *uu_ptr, *ub_ptr, *bb_ptr, *cnt, *part;
    int2 *bu_cv, *uu_cv, *ub_cv, *bb_cv;
    cudaGetSymbolAddress((void**)&bu_ptr, g_bu_ptr);
    cudaGetSymbolAddress((void**)&bu_cv,  g_bu_cv);
    cudaGetSymbolAddress((void**)&uu_ptr, g_uu_ptr);
    cudaGetSymbolAddress((void**)&uu_cv,  g_uu_cv);
    cudaGetSymbolAddress((void**)&ub_ptr, g_ub_ptr);
    cudaGetSymbolAddress((void**)&ub_cv,  g_ub_cv);
    cudaGetSymbolAddress((void**)&bb_ptr, g_bb_ptr);
    cudaGetSymbolAddress((void**)&bb_cv,  g_bb_cv);
    cudaGetSymbolAddress((void**)&cnt, g_cnt);
    cudaGetSymbolAddress((void**)&part, g_part);

    gemm_tc_kernel<<<NUSR_PAD / GBM, 256>>>(user_feat, W_user, uS, NUSR);
    gemm_tc_kernel<<<NBIZ_PAD / GBM, 256>>>(biz_feat,  W_biz,  bS, NBIZ);
    f2h_kernel<<<(NUSR_PAD * D / 4 + 255) / 256, 256>>>(uS, uhA, NUSR_PAD * D / 4);
    f2h_kernel<<<(NBIZ_PAD * D / 4 + 255) / 256, 256>>>(bS, bhA, NBIZ_PAD * D / 4);

    build_csr(ub_u,  ub_b,  val_bu, bu_ptr, bu_cv, cnt, part, NUSR, EUB);
    build_csr(uu_dst, uu_src, uu_val, uu_ptr, uu_cv, cnt, part, NUSR, EUU);
    build_csr(ub_b,  ub_u,  val_ub, ub_ptr, ub_cv, cnt, part, NBIZ, EUB);
    build_csr(bb_dst, bb_src, bb_val, bb_ptr, bb_cv, cnt, part, NBIZ, EBB);

    __half2* u_cur = uhA; __half2* u_new = uhB;
    __half2* b_cur = bhA; __half2* b_new = bhB;

    const int totWarps = NUSR + NBIZ;
    const int spmmBlocks = (totWarps * 32 + 255) / 256;

    for (int layer = 0; layer < 3; layer++) {
        spmm_layer_kernel<<<spmmBlocks, 256>>>(
            bu_ptr, bu_cv, uu_ptr, uu_cv, ub_ptr, ub_cv, bb_ptr, bb_cv,
            u_cur, b_cur, u_new, b_new, uS, bS, layer < 2 ? 1 : 0);
        __half2* t;
        t = u_cur; u_cur = u_new; u_new = t;
        t = b_cur; b_cur = b_new; b_new = t;
    }

    const float inv = 1.0f / 4.0f;
    l2norm_kernel<<<(NUSR * 32 + 255) / 256, 256>>>(uS, out, NUSR, inv);
    l2norm_kernel<<<(NBIZ * 32 + 255) / 256, 256>>>(bS, out + (size_t)NUSR * D,
                                                    NBIZ, inv);
    (void)n_in; (void)in_sizes; (void)out_size;
}

// round 8
// speedup vs baseline: 3.5021x; 1.0989x over previous
#include <cuda_runtime.h>
#include <cuda_fp16.h>
#include <mma.h>
#include <cstdint>

using namespace nvcuda;

#define NUSR 100000
#define NBIZ 20000
#define NUSR_PAD 100096
#define NBIZ_PAD 20096
#define EUB  3200000
#define EUU  1600000
#define EBB  320000
#define INDIM 384
#define D    128
#define DH   64

__device__ float g_uS[(size_t)NUSR_PAD * D];
__device__ float g_bS[(size_t)NBIZ_PAD * D];
__device__ __half2 g_uhA[(size_t)NUSR_PAD * DH];
__device__ __half2 g_uhB[(size_t)NUSR_PAD * DH];
__device__ __half2 g_bhA[(size_t)NBIZ_PAD * DH];
__device__ __half2 g_bhB[(size_t)NBIZ_PAD * DH];

__device__ int  g_bu_ptr[NUSR + 1];
__device__ int2 g_bu_cv[EUB];
__device__ int  g_uu_ptr[NUSR + 1];
__device__ int2 g_uu_cv[EUU];
__device__ int  g_ub_ptr[NBIZ + 1];
__device__ int2 g_ub_cv[EUB];
__device__ int  g_bb_ptr[NBIZ + 1];
__device__ int2 g_bb_cv[EBB];

// count/cursor arrays for all 4 CSRs, contiguous for one memset
#define OFF_BU 0
#define OFF_UU NUSR
#define OFF_UB (2 * NUSR)
#define OFF_BB (2 * NUSR + NBIZ)
#define CNT4_TOT (2 * NUSR + 2 * NBIZ)
__device__ int g_cnt4[CNT4_TOT];
__device__ int g_part4[4 * 128];

// ================= CSR build (batched) =======================================
// UB edges: one pass updates both user-side and biz-side counts
__global__ void hist_ub_kernel(const int* __restrict__ ub_u,
                               const int* __restrict__ ub_b,
                               int* __restrict__ cnt4) {
    int i = blockIdx.x * blockDim.x + threadIdx.x;
    if (i >= EUB) return;
    atomicAdd(&cnt4[OFF_BU + ub_u[i]], 1);
    atomicAdd(&cnt4[OFF_UB + ub_b[i]], 1);
}

__global__ void hist_kernel(const int* __restrict__ dst, int* __restrict__ cnt,
                            int E) {
    int i = blockIdx.x * blockDim.x + threadIdx.x;
    if (i < E) atomicAdd(&cnt[dst[i]], 1);
}

#define SCAN_BLK 1024
// batched scans: blockIdx.y selects matrix {bu,uu,ub,bb}
__global__ void scan1_4_kernel(const int* __restrict__ cnt4,
                               int* __restrict__ bu_ptr, int* __restrict__ uu_ptr,
                               int* __restrict__ ub_ptr, int* __restrict__ bb_ptr,
                               int* __restrict__ part4) {
    __shared__ int sh[SCAN_BLK];
    const int y = blockIdx.y;
    const int off = (y == 0) ? OFF_BU : (y == 1) ? OFF_UU : (y == 2) ? OFF_UB : OFF_BB;
    const int n   = (y < 2) ? NUSR : NBIZ;
    int* out = (y == 0) ? bu_ptr : (y == 1) ? uu_ptr : (y == 2) ? ub_ptr : bb_ptr;
    int i = blockIdx.x * SCAN_BLK + threadIdx.x;
    int v = (i < n) ? cnt4[off + i] : 0;
    sh[threadIdx.x] = v;
    __syncthreads();
#pragma unroll
    for (int o = 1; o < SCAN_BLK; o <<= 1) {
        int t = (threadIdx.x >= o) ? sh[threadIdx.x - o] : 0;
        __syncthreads();
        sh[threadIdx.x] += t;
        __syncthreads();
    }
    if (i < n) out[i] = sh[threadIdx.x] - v;
    if (threadIdx.x == SCAN_BLK - 1) part4[y * 128 + blockIdx.x] = sh[threadIdx.x];
}

__global__ void scan2_4_kernel(int* __restrict__ part4) {
    __shared__ int sh[128];
    const int y = blockIdx.y;
    const int nb = (y < 2) ? ((NUSR + SCAN_BLK - 1) / SCAN_BLK)
                           : ((NBIZ + SCAN_BLK - 1) / SCAN_BLK);
    int v = (threadIdx.x < nb) ? part4[y * 128 + threadIdx.x] : 0;
    sh[threadIdx.x] = v;
    __syncthreads();
#pragma unroll
    for (int o = 1; o < 128; o <<= 1) {
        int t = (threadIdx.x >= o) ? sh[threadIdx.x - o] : 0;
        __syncthreads();
        sh[threadIdx.x] += t;
        __syncthreads();
    }
    if (threadIdx.x < nb) part4[y * 128 + threadIdx.x] = sh[threadIdx.x] - v;
}

__global__ void scan3_4_kernel(int* __restrict__ bu_ptr, int* __restrict__ uu_ptr,
                               int* __restrict__ ub_ptr, int* __restrict__ bb_ptr,
                               const int* __restrict__ part4) {
    const int y = blockIdx.y;
    const int n = (y < 2) ? NUSR : NBIZ;
    const int E = (y == 0) ? EUB : (y == 1) ? EUU : (y == 2) ? EUB : EBB;
    int* out = (y == 0) ? bu_ptr : (y == 1) ? uu_ptr : (y == 2) ? ub_ptr : bb_ptr;
    int i = blockIdx.x * blockDim.x + threadIdx.x;
    if (i < n) out[i] += part4[y * 128 + i / SCAN_BLK];
    if (i == 0) out[n] = E;
}

// UB edges: one pass fills both CSRs
__global__ void fill_ub_kernel(const int* __restrict__ ub_u, const int* __restrict__ ub_b,
                               const float* __restrict__ val_ub, const float* __restrict__ val_bu,
                               const int* __restrict__ bu_ptr, const int* __restrict__ ub_ptr,
                               int* __restrict__ cnt4,
                               int2* __restrict__ bu_cv, int2* __restrict__ ub_cv) {
    int i = blockIdx.x * blockDim.x + threadIdx.x;
    if (i >= EUB) return;
    int u = ub_u[i];
    int b = ub_b[i];
    int pu = bu_ptr[u] + atomicAdd(&cnt4[OFF_BU + u], 1);
    bu_cv[pu] = make_int2(b, __float_as_int(val_bu[i]));
    int pb = ub_ptr[b] + atomicAdd(&cnt4[OFF_UB + b], 1);
    ub_cv[pb] = make_int2(u, __float_as_int(val_ub[i]));
}

__global__ void fill_kernel(const int* __restrict__ dst, const int* __restrict__ src,
                            const float* __restrict__ val,
                            const int* __restrict__ ptr, int* __restrict__ cursor,
                            int2* __restrict__ cv, int E) {
    int i = blockIdx.x * blockDim.x + threadIdx.x;
    if (i >= E) return;
    int d = dst[i];
    int pos = ptr[d] + atomicAdd(&cursor[d], 1);
    cv[pos] = make_int2(src[i], __float_as_int(val[i]));
}

// ================= tensor-core GEMM: S[M,128] = A[M,384] @ W[384,128] ========
#define GBM 128
#define GBK 16
__global__ void gemm_tc_kernel(const float* __restrict__ A,
                               const float* __restrict__ W,
                               float* __restrict__ S, int M) {
    __shared__ __half Ash[GBM][GBK + 8];
    __shared__ __half Wsh[GBK][D + 8];
    const int tid  = threadIdx.x;
    const int warp = tid >> 5;
    const int wr   = warp >> 1;
    const int wc   = warp & 1;
    const int row0 = blockIdx.x * GBM;

    wmma::fragment<wmma::accumulator, 16, 16, 16, float> acc[2][4];
#pragma unroll
    for (int r = 0; r < 2; r++)
#pragma unroll
        for (int c = 0; c < 4; c++) wmma::fill_fragment(acc[r][c], 0.0f);

    for (int k0 = 0; k0 < INDIM; k0 += GBK) {
#pragma unroll
        for (int i = 0; i < 8; i++) {
            int idx = tid + i * 256;
            int r  = idx >> 4;
            int kk = idx & 15;
            int gr = row0 + r;
            float a = (gr < M) ? __ldg(A + (size_t)gr * INDIM + k0 + kk) : 0.f;
            Ash[r][kk] = __float2half_rn(a);
        }
#pragma unroll
        for (int i = 0; i < 8; i++) {
            int idx = tid + i * 256;
            int kk = idx >> 7;
            int c  = idx & 127;
            Wsh[kk][c] = __float2half_rn(__ldg(W + (size_t)(k0 + kk) * D + c));
        }
        __syncthreads();

        wmma::fragment<wmma::matrix_a, 16, 16, 16, __half, wmma::row_major> fa[2];
        wmma::fragment<wmma::matrix_b, 16, 16, 16, __half, wmma::row_major> fb[4];
#pragma unroll
        for (int r = 0; r < 2; r++)
            wmma::load_matrix_sync(fa[r], &Ash[wr * 32 + r * 16][0], GBK + 8);
#pragma unroll
        for (int c = 0; c < 4; c++)
            wmma::load_matrix_sync(fb[c], &Wsh[0][wc * 64 + c * 16], D + 8);
#pragma unroll
        for (int r = 0; r < 2; r++)
#pragma unroll
            for (int c = 0; c < 4; c++)
                wmma::mma_sync(acc[r][c], fa[r], fb[c], acc[r][c]);
        __syncthreads();
    }
#pragma unroll
    for (int r = 0; r < 2; r++)
#pragma unroll
        for (int c = 0; c < 4; c++)
            wmma::store_matrix_sync(
                S + (size_t)(row0 + wr * 32 + r * 16) * D + wc * 64 + c * 16,
                acc[r][c], D, wmma::mem_row_major);
}

__global__ void f2h_kernel(const float* __restrict__ S, __half2* __restrict__ H,
                           int n4) {
    int i = blockIdx.x * blockDim.x + threadIdx.x;
    if (i >= n4) return;
    float4 v = reinterpret_cast<const float4*>(S)[i];
    uint2 h;
    __half2 h0 = __float22half2_rn(make_float2(v.x, v.y));
    __half2 h1 = __float22half2_rn(make_float2(v.z, v.w));
    h.x = *reinterpret_cast<uint32_t*>(&h0);
    h.y = *reinterpret_cast<uint32_t*>(&h1);
    reinterpret_cast<uint2*>(H)[i] = h;
}

// ================= fused gather SpMM layer (fp16 source rows) ================
__device__ __forceinline__ void gather_row_h(const int* __restrict__ ptr,
                                             const int2* __restrict__ cv,
                                             const __half2* __restrict__ x,
                                             int row, int lane, float4& acc) {
    int s = __ldg(ptr + row);
    int e = __ldg(ptr + row + 1);
    for (int base = s; base < e; base += 32) {
        int rem = e - base;   // > 0, warp-uniform
        int c = 0; float v = 0.f;
        if (lane < rem) {
            int2 p = __ldg(cv + base + lane);
            c = p.x; v = __int_as_float(p.y);
        }
#pragma unroll
        for (int jb = 0; jb < 32; jb += 8) {
            if (jb >= rem) break;   // warp-uniform
#pragma unroll
            for (int jj = 0; jj < 8; jj++) {
                int   cj = __shfl_sync(0xffffffffu, c, jb + jj);
                float vj = __shfl_sync(0xffffffffu, v, jb + jj);
                uint2 raw = __ldg(reinterpret_cast<const uint2*>(x + (size_t)cj * DH) + lane);
                __half2 p0 = *reinterpret_cast<__half2*>(&raw.x);
                __half2 p1 = *reinterpret_cast<__half2*>(&raw.y);
                float2 f0 = __half22float2(p0);
                float2 f1 = __half22float2(p1);
                acc.x += vj * f0.x; acc.y += vj * f0.y;
                acc.z += vj * f1.x; acc.w += vj * f1.y;
            }
        }
    }
}

__global__ void spmm_layer_kernel(const int* __restrict__ bu_ptr, const int2* __restrict__ bu_cv,
                                  const int* __restrict__ uu_ptr, const int2* __restrict__ uu_cv,
                                  const int* __restrict__ ub_ptr, const int2* __restrict__ ub_cv,
                                  const int* __restrict__ bb_ptr, const int2* __restrict__ bb_cv,
                                  const __half2* __restrict__ u_cur,
                                  const __half2* __restrict__ b_cur,
                                  __half2* __restrict__ u_new,
                                  __half2* __restrict__ b_new,
                                  float* __restrict__ uS, float* __restrict__ bS,
                                  int write_new) {
    const int lane = threadIdx.x & 31;
    const int w = (blockIdx.x * blockDim.x + threadIdx.x) >> 5;
    float4 acc = make_float4(0.f, 0.f, 0.f, 0.f);
    if (w < NUSR) {
        const int row = w;
        gather_row_h(bu_ptr, bu_cv, b_cur, row, lane, acc);
        gather_row_h(uu_ptr, uu_cv, u_cur, row, lane, acc);
        float4* sump = reinterpret_cast<float4*>(uS + (size_t)row * D) + lane;
        float4 s = *sump;
        s.x += acc.x; s.y += acc.y; s.z += acc.z; s.w += acc.w;
        *sump = s;
        if (write_new) {
            uint2 h;
            __half2 h0 = __float22half2_rn(make_float2(acc.x, acc.y));
            __half2 h1 = __float22half2_rn(make_float2(acc.z, acc.w));
            h.x = *reinterpret_cast<uint32_t*>(&h0);
            h.y = *reinterpret_cast<uint32_t*>(&h1);
            *reinterpret_cast<uint2*>(u_new + (size_t)row * DH + lane * 2) = h;
        }
    } else if (w < NUSR + NBIZ) {
        const int row = w - NUSR;
        gather_row_h(ub_ptr, ub_cv, u_cur, row, lane, acc);
        gather_row_h(bb_ptr, bb_cv, b_cur, row, lane, acc);
        float4* sump = reinterpret_cast<float4*>(bS + (size_t)row * D) + lane;
        float4 s = *sump;
        s.x += acc.x; s.y += acc.y; s.z += acc.z; s.w += acc.w;
        *sump = s;
        if (write_new) {
            uint2 h;
            __half2 h0 = __float22half2_rn(make_float2(acc.x, acc.y));
            __half2 h1 = __float22half2_rn(make_float2(acc.z, acc.w));
            h.x = *reinterpret_cast<uint32_t*>(&h0);
            h.y = *reinterpret_cast<uint32_t*>(&h1);
            *reinterpret_cast<uint2*>(b_new + (size_t)row * DH + lane * 2) = h;
        }
    }
}

// ================= epilogue: out = l2norm(sum * inv) =========================
__global__ void l2norm_kernel(const float* __restrict__ s,
                              float* __restrict__ out, int nrows, float inv) {
    const int lane = threadIdx.x & 31;
    const int row  = (blockIdx.x * blockDim.x + threadIdx.x) >> 5;
    if (row >= nrows) return;
    float4 v = reinterpret_cast<const float4*>(s + (size_t)row * D)[lane];
    v.x *= inv; v.y *= inv; v.z *= inv; v.w *= inv;
    float ss = v.x * v.x + v.y * v.y + v.z * v.z + v.w * v.w;
#pragma unroll
    for (int o = 16; o; o >>= 1) ss += __shfl_xor_sync(0xffffffffu, ss, o);
    float nrm = sqrtf(ss);
    float sc = 1.0f / fmaxf(nrm, 1e-12f);
    v.x *= sc; v.y *= sc; v.z *= sc; v.w *= sc;
    reinterpret_cast<float4*>(out + (size_t)row * D)[lane] = v;
}

// ================= launcher ====================================================
extern "C" void kernel_launch(void* const* d_in, const int* in_sizes, int n_in,
                              void* d_out, int out_size) {
    const float* user_feat = (const float*)d_in[0];
    const float* biz_feat  = (const float*)d_in[1];
    const float* W_user    = (const float*)d_in[2];
    const float* W_biz     = (const float*)d_in[3];
    const int*   ub_u      = (const int*)  d_in[4];
    const int*   ub_b      = (const int*)  d_in[5];
    const float* val_ub    = (const float*)d_in[6];
    const float* val_bu    = (const float*)d_in[7];
    const int*   uu_src    = (const int*)  d_in[8];
    const int*   uu_dst    = (const int*)  d_in[9];
    const float* uu_val    = (const float*)d_in[10];
    const int*   bb_src    = (const int*)  d_in[11];
    const int*   bb_dst    = (const int*)  d_in[12];
    const float* bb_val    = (const float*)d_in[13];
    float* out = (float*)d_out;

    float *uS, *bS;
    __half2 *uhA, *uhB, *bhA, *bhB;
    cudaGetSymbolAddress((void**)&uS, g_uS);
    cudaGetSymbolAddress((void**)&bS, g_bS);
    cudaGetSymbolAddress((void**)&uhA, g_uhA);
    cudaGetSymbolAddress((void**)&uhB, g_uhB);
    cudaGetSymbolAddress((void**)&bhA, g_bhA);
    cudaGetSymbolAddress((void**)&bhB, g_bhB);

    int *bu_ptr, *uu_ptr, *ub_ptr, *bb_ptr, *cnt4, *part4;
    int2 *bu_cv, *uu_cv, *ub_cv, *bb_cv;
    cudaGetSymbolAddress((void**)&bu_ptr, g_bu_ptr);
    cudaGetSymbolAddress((void**)&bu_cv,  g_bu_cv);
    cudaGetSymbolAddress((void**)&uu_ptr, g_uu_ptr);
    cudaGetSymbolAddress((void**)&uu_cv,  g_uu_cv);
    cudaGetSymbolAddress((void**)&ub_ptr, g_ub_ptr);
    cudaGetSymbolAddress((void**)&ub_cv,  g_ub_cv);
    cudaGetSymbolAddress((void**)&bb_ptr, g_bb_ptr);
    cudaGetSymbolAddress((void**)&bb_cv,  g_bb_cv);
    cudaGetSymbolAddress((void**)&cnt4, g_cnt4);
    cudaGetSymbolAddress((void**)&part4, g_part4);

    // one-time infra (identical work every call; resources reused)
    static cudaStream_t s2 = nullptr;
    static cudaEvent_t evFork = nullptr, evJoin = nullptr;
    if (s2 == nullptr) {
        cudaStreamCreateWithFlags(&s2, cudaStreamNonBlocking);
        cudaEventCreateWithFlags(&evFork, cudaEventDisableTiming);
        cudaEventCreateWithFlags(&evJoin, cudaEventDisableTiming);
    }

    // ---- fork: CSR build chain on s2, GEMM chain on stream 0 ----
    cudaEventRecord(evFork, 0);
    cudaStreamWaitEvent(s2, evFork, 0);

    // CSR build (stream s2)
    cudaMemsetAsync(cnt4, 0, CNT4_TOT * sizeof(int), s2);
    hist_ub_kernel<<<(EUB + 255) / 256, 256, 0, s2>>>(ub_u, ub_b, cnt4);
    hist_kernel<<<(EUU + 255) / 256, 256, 0, s2>>>(uu_dst, cnt4 + OFF_UU, EUU);
    hist_kernel<<<(EBB + 255) / 256, 256, 0, s2>>>(bb_dst, cnt4 + OFF_BB, EBB);
    {
        dim3 g1((NUSR + SCAN_BLK - 1) / SCAN_BLK, 4);
        scan1_4_kernel<<<g1, SCAN_BLK, 0, s2>>>(cnt4, bu_ptr, uu_ptr, ub_ptr, bb_ptr, part4);
        dim3 g2(1, 4);
        scan2_4_kernel<<<g2, 128, 0, s2>>>(part4);
        dim3 g3((NUSR + 255) / 256, 4);
        scan3_4_kernel<<<g3, 256, 0, s2>>>(bu_ptr, uu_ptr, ub_ptr, bb_ptr, part4);
    }
    cudaMemsetAsync(cnt4, 0, CNT4_TOT * sizeof(int), s2);
    fill_ub_kernel<<<(EUB + 255) / 256, 256, 0, s2>>>(ub_u, ub_b, val_ub, val_bu,
                                                      bu_ptr, ub_ptr, cnt4, bu_cv, ub_cv);
    fill_kernel<<<(EUU + 255) / 256, 256, 0, s2>>>(uu_dst, uu_src, uu_val,
                                                   uu_ptr, cnt4 + OFF_UU, uu_cv, EUU);
    fill_kernel<<<(EBB + 255) / 256, 256, 0, s2>>>(bb_dst, bb_src, bb_val,
                                                   bb_ptr, cnt4 + OFF_BB, bb_cv, EBB);
    cudaEventRecord(evJoin, s2);

    // GEMM + f2h (stream 0, concurrent with CSR build)
    gemm_tc_kernel<<<NUSR_PAD / GBM, 256>>>(user_feat, W_user, uS, NUSR);
    gemm_tc_kernel<<<NBIZ_PAD / GBM, 256>>>(biz_feat,  W_biz,  bS, NBIZ);
    f2h_kernel<<<(NUSR_PAD * D / 4 + 255) / 256, 256>>>(uS, uhA, NUSR_PAD * D / 4);
    f2h_kernel<<<(NBIZ_PAD * D / 4 + 255) / 256, 256>>>(bS, bhA, NBIZ_PAD * D / 4);

    // ---- join ----
    cudaStreamWaitEvent(0, evJoin, 0);

    __half2* u_cur = uhA; __half2* u_new = uhB;
    __half2* b_cur = bhA; __half2* b_new = bhB;

    const int totWarps = NUSR + NBIZ;
    const int spmmBlocks = (totWarps * 32 + 255) / 256;

    for (int layer = 0; layer < 3; layer++) {
        spmm_layer_kernel<<<spmmBlocks, 256>>>(
            bu_ptr, bu_cv, uu_ptr, uu_cv, ub_ptr, ub_cv, bb_ptr, bb_cv,
            u_cur, b_cur, u_new, b_new, uS, bS, layer < 2 ? 1 : 0);
        __half2* t;
        t = u_cur; u_cur = u_new; u_new = t;
        t = b_cur; b_cur = b_new; b_new = t;
    }

    const float inv = 1.0f / 4.0f;
    l2norm_kernel<<<(NUSR * 32 + 255) / 256, 256>>>(uS, out, NUSR, inv);
    l2norm_kernel<<<(NBIZ * 32 + 255) / 256, 256>>>(bS, out + (size_t)NUSR * D,
                                                    NBIZ, inv);
    (void)n_in; (void)in_sizes; (void)out_size;
}

// round 9
// speedup vs baseline: 3.5129x; 1.0031x over previous
#include <cuda_runtime.h>
#include <cuda_fp16.h>
#include <mma.h>
#include <cstdint>

using namespace nvcuda;

#define NUSR 100000
#define NBIZ 20000
#define NUSR_PAD 100096
#define NBIZ_PAD 20096
#define EUB  3200000
#define EUU  1600000
#define EBB  320000
#define EALL (EUB + EUU + EBB)
#define INDIM 384
#define D    128
#define DH   64

__device__ float g_uS[(size_t)NUSR_PAD * D];
__device__ float g_bS[(size_t)NBIZ_PAD * D];
__device__ __half2 g_uhA[(size_t)NUSR_PAD * DH];
__device__ __half2 g_uhB[(size_t)NUSR_PAD * DH];
__device__ __half2 g_bhA[(size_t)NBIZ_PAD * DH];
__device__ __half2 g_bhB[(size_t)NBIZ_PAD * DH];

__device__ int  g_bu_ptr[NUSR + 1];
__device__ int2 g_bu_cv[EUB];
__device__ int  g_uu_ptr[NUSR + 1];
__device__ int2 g_uu_cv[EUU];
__device__ int  g_ub_ptr[NBIZ + 1];
__device__ int2 g_ub_cv[EUB];
__device__ int  g_bb_ptr[NBIZ + 1];
__device__ int2 g_bb_cv[EBB];

#define OFF_BU 0
#define OFF_UU NUSR
#define OFF_UB (2 * NUSR)
#define OFF_BB (2 * NUSR + NBIZ)
#define CNT4_TOT (2 * NUSR + 2 * NBIZ)
__device__ int g_cnt4[CNT4_TOT];
__device__ int g_part4[4 * 128];

// ================= CSR build (fully batched) ==================================
// ONE kernel for all histograms
__global__ void hist_all_kernel(const int* __restrict__ ub_u, const int* __restrict__ ub_b,
                                const int* __restrict__ uu_dst, const int* __restrict__ bb_dst,
                                int* __restrict__ cnt4) {
    int i = blockIdx.x * blockDim.x + threadIdx.x;
    if (i < EUB) {
        atomicAdd(&cnt4[OFF_BU + ub_u[i]], 1);
        atomicAdd(&cnt4[OFF_UB + ub_b[i]], 1);
    } else if (i < EUB + EUU) {
        atomicAdd(&cnt4[OFF_UU + uu_dst[i - EUB]], 1);
    } else if (i < EALL) {
        atomicAdd(&cnt4[OFF_BB + bb_dst[i - EUB - EUU]], 1);
    }
}

#define SCAN_BLK 1024
__global__ void scan1_4_kernel(const int* __restrict__ cnt4,
                               int* __restrict__ bu_ptr, int* __restrict__ uu_ptr,
                               int* __restrict__ ub_ptr, int* __restrict__ bb_ptr,
                               int* __restrict__ part4) {
    __shared__ int sh[SCAN_BLK];
    const int y = blockIdx.y;
    const int off = (y == 0) ? OFF_BU : (y == 1) ? OFF_UU : (y == 2) ? OFF_UB : OFF_BB;
    const int n   = (y < 2) ? NUSR : NBIZ;
    int* out = (y == 0) ? bu_ptr : (y == 1) ? uu_ptr : (y == 2) ? ub_ptr : bb_ptr;
    int i = blockIdx.x * SCAN_BLK + threadIdx.x;
    int v = (i < n) ? cnt4[off + i] : 0;
    sh[threadIdx.x] = v;
    __syncthreads();
#pragma unroll
    for (int o = 1; o < SCAN_BLK; o <<= 1) {
        int t = (threadIdx.x >= o) ? sh[threadIdx.x - o] : 0;
        __syncthreads();
        sh[threadIdx.x] += t;
        __syncthreads();
    }
    if (i < n) out[i] = sh[threadIdx.x] - v;
    if (threadIdx.x == SCAN_BLK - 1) part4[y * 128 + blockIdx.x] = sh[threadIdx.x];
}

__global__ void scan2_4_kernel(int* __restrict__ part4) {
    __shared__ int sh[128];
    const int y = blockIdx.y;
    const int nb = (y < 2) ? ((NUSR + SCAN_BLK - 1) / SCAN_BLK)
                           : ((NBIZ + SCAN_BLK - 1) / SCAN_BLK);
    int v = (threadIdx.x < nb) ? part4[y * 128 + threadIdx.x] : 0;
    sh[threadIdx.x] = v;
    __syncthreads();
#pragma unroll
    for (int o = 1; o < 128; o <<= 1) {
        int t = (threadIdx.x >= o) ? sh[threadIdx.x - o] : 0;
        __syncthreads();
        sh[threadIdx.x] += t;
        __syncthreads();
    }
    if (threadIdx.x < nb) part4[y * 128 + threadIdx.x] = sh[threadIdx.x] - v;
}

__global__ void scan3_4_kernel(int* __restrict__ bu_ptr, int* __restrict__ uu_ptr,
                               int* __restrict__ ub_ptr, int* __restrict__ bb_ptr,
                               const int* __restrict__ part4) {
    const int y = blockIdx.y;
    const int n = (y < 2) ? NUSR : NBIZ;
    const int E = (y == 0) ? EUB : (y == 1) ? EUU : (y == 2) ? EUB : EBB;
    int* out = (y == 0) ? bu_ptr : (y == 1) ? uu_ptr : (y == 2) ? ub_ptr : bb_ptr;
    int i = blockIdx.x * blockDim.x + threadIdx.x;
    if (i < n) out[i] += part4[y * 128 + i / SCAN_BLK];
    if (i == 0) out[n] = E;
}

// ONE kernel for all fills
__global__ void fill_all_kernel(const int* __restrict__ ub_u, const int* __restrict__ ub_b,
                                const float* __restrict__ val_ub, const float* __restrict__ val_bu,
                                const int* __restrict__ uu_src, const int* __restrict__ uu_dst,
                                const float* __restrict__ uu_val,
                                const int* __restrict__ bb_src, const int* __restrict__ bb_dst,
                                const float* __restrict__ bb_val,
                                const int* __restrict__ bu_ptr, const int* __restrict__ uu_ptr,
                                const int* __restrict__ ub_ptr, const int* __restrict__ bb_ptr,
                                int* __restrict__ cnt4,
                                int2* __restrict__ bu_cv, int2* __restrict__ uu_cv,
                                int2* __restrict__ ub_cv, int2* __restrict__ bb_cv) {
    int i = blockIdx.x * blockDim.x + threadIdx.x;
    if (i < EUB) {
        int u = ub_u[i];
        int b = ub_b[i];
        int pu = bu_ptr[u] + atomicAdd(&cnt4[OFF_BU + u], 1);
        bu_cv[pu] = make_int2(b, __float_as_int(val_bu[i]));
        int pb = ub_ptr[b] + atomicAdd(&cnt4[OFF_UB + b], 1);
        ub_cv[pb] = make_int2(u, __float_as_int(val_ub[i]));
    } else if (i < EUB + EUU) {
        int j = i - EUB;
        int d = uu_dst[j];
        int pos = uu_ptr[d] + atomicAdd(&cnt4[OFF_UU + d], 1);
        uu_cv[pos] = make_int2(uu_src[j], __float_as_int(uu_val[j]));
    } else if (i < EALL) {
        int j = i - EUB - EUU;
        int d = bb_dst[j];
        int pos = bb_ptr[d] + atomicAdd(&cnt4[OFF_BB + d], 1);
        bb_cv[pos] = make_int2(bb_src[j], __float_as_int(bb_val[j]));
    }
}

// ================= tensor-core GEMM + fused f2h ==============================
// S[M,128] fp32 AND H[M,64] half2, one kernel.
#define GBM 128
#define GBK 16
__global__ void gemm_tc_kernel(const float* __restrict__ A,
                               const float* __restrict__ W,
                               float* __restrict__ S,
                               __half2* __restrict__ H, int M) {
    __shared__ __half Ash[GBM][GBK + 8];
    __shared__ __half Wsh[GBK][D + 8];
    const int tid  = threadIdx.x;
    const int warp = tid >> 5;
    const int wr   = warp >> 1;
    const int wc   = warp & 1;
    const int row0 = blockIdx.x * GBM;

    wmma::fragment<wmma::accumulator, 16, 16, 16, float> acc[2][4];
#pragma unroll
    for (int r = 0; r < 2; r++)
#pragma unroll
        for (int c = 0; c < 4; c++) wmma::fill_fragment(acc[r][c], 0.0f);

    for (int k0 = 0; k0 < INDIM; k0 += GBK) {
#pragma unroll
        for (int i = 0; i < 8; i++) {
            int idx = tid + i * 256;
            int r  = idx >> 4;
            int kk = idx & 15;
            int gr = row0 + r;
            float a = (gr < M) ? __ldg(A + (size_t)gr * INDIM + k0 + kk) : 0.f;
            Ash[r][kk] = __float2half_rn(a);
        }
#pragma unroll
        for (int i = 0; i < 8; i++) {
            int idx = tid + i * 256;
            int kk = idx >> 7;
            int c  = idx & 127;
            Wsh[kk][c] = __float2half_rn(__ldg(W + (size_t)(k0 + kk) * D + c));
        }
        __syncthreads();

        wmma::fragment<wmma::matrix_a, 16, 16, 16, __half, wmma::row_major> fa[2];
        wmma::fragment<wmma::matrix_b, 16, 16, 16, __half, wmma::row_major> fb[4];
#pragma unroll
        for (int r = 0; r < 2; r++)
            wmma::load_matrix_sync(fa[r], &Ash[wr * 32 + r * 16][0], GBK + 8);
#pragma unroll
        for (int c = 0; c < 4; c++)
            wmma::load_matrix_sync(fb[c], &Wsh[0][wc * 64 + c * 16], D + 8);
#pragma unroll
        for (int r = 0; r < 2; r++)
#pragma unroll
            for (int c = 0; c < 4; c++)
                wmma::mma_sync(acc[r][c], fa[r], fb[c], acc[r][c]);
        __syncthreads();
    }
#pragma unroll
    for (int r = 0; r < 2; r++)
#pragma unroll
        for (int c = 0; c < 4; c++)
            wmma::store_matrix_sync(
                S + (size_t)(row0 + wr * 32 + r * 16) * D + wc * 64 + c * 16,
                acc[r][c], D, wmma::mem_row_major);
    // fused f2h: block re-reads its own (L2-hot) fp32 tile; __syncthreads
    // orders intra-block global stores before these loads.
    __syncthreads();
    const int n4 = GBM * D / 4;   // 4096 float4 in this block's tile
    for (int i = tid; i < n4; i += 256) {
        float4 v = reinterpret_cast<const float4*>(S + (size_t)row0 * D)[i];
        uint2 h;
        __half2 h0 = __float22half2_rn(make_float2(v.x, v.y));
        __half2 h1 = __float22half2_rn(make_float2(v.z, v.w));
        h.x = *reinterpret_cast<uint32_t*>(&h0);
        h.y = *reinterpret_cast<uint32_t*>(&h1);
        reinterpret_cast<uint2*>(H + (size_t)row0 * DH)[i] = h;
    }
}

// ================= fused gather SpMM layer (fp16 source rows) ================
__device__ __forceinline__ void gather_row_h(const int* __restrict__ ptr,
                                             const int2* __restrict__ cv,
                                             const __half2* __restrict__ x,
                                             int row, int lane, float4& acc) {
    int s = __ldg(ptr + row);
    int e = __ldg(ptr + row + 1);
    for (int base = s; base < e; base += 32) {
        int rem = e - base;   // > 0, warp-uniform
        int c = 0; float v = 0.f;
        if (lane < rem) {
            int2 p = __ldg(cv + base + lane);
            c = p.x; v = __int_as_float(p.y);
        }
#pragma unroll
        for (int jb = 0; jb < 32; jb += 8) {
            if (jb >= rem) break;   // warp-uniform
#pragma unroll
            for (int jj = 0; jj < 8; jj++) {
                int   cj = __shfl_sync(0xffffffffu, c, jb + jj);
                float vj = __shfl_sync(0xffffffffu, v, jb + jj);
                uint2 raw = __ldg(reinterpret_cast<const uint2*>(x + (size_t)cj * DH) + lane);
                __half2 p0 = *reinterpret_cast<__half2*>(&raw.x);
                __half2 p1 = *reinterpret_cast<__half2*>(&raw.y);
                float2 f0 = __half22float2(p0);
                float2 f1 = __half22float2(p1);
                acc.x += vj * f0.x; acc.y += vj * f0.y;
                acc.z += vj * f1.x; acc.w += vj * f1.y;
            }
        }
    }
}

// final==0: s += acc stored to sums, acc stored fp16 to *_new
// final==1: out = l2norm((s + acc) * inv) written directly; no other stores
__global__ void spmm_layer_kernel(const int* __restrict__ bu_ptr, const int2* __restrict__ bu_cv,
                                  const int* __restrict__ uu_ptr, const int2* __restrict__ uu_cv,
                                  const int* __restrict__ ub_ptr, const int2* __restrict__ ub_cv,
                                  const int* __restrict__ bb_ptr, const int2* __restrict__ bb_cv,
                                  const __half2* __restrict__ u_cur,
                                  const __half2* __restrict__ b_cur,
                                  __half2* __restrict__ u_new,
                                  __half2* __restrict__ b_new,
                                  float* __restrict__ uS, float* __restrict__ bS,
                                  float* __restrict__ out, int final_layer) {
    const int lane = threadIdx.x & 31;
    const int w = (blockIdx.x * blockDim.x + threadIdx.x) >> 5;
    float4 acc = make_float4(0.f, 0.f, 0.f, 0.f);
    int row; const float* sumbase; float* outrow;
    if (w < NUSR) {
        row = w;
        gather_row_h(bu_ptr, bu_cv, b_cur, row, lane, acc);
        gather_row_h(uu_ptr, uu_cv, u_cur, row, lane, acc);
        sumbase = uS + (size_t)row * D;
        outrow  = out + (size_t)row * D;
    } else if (w < NUSR + NBIZ) {
        row = w - NUSR;
        gather_row_h(ub_ptr, ub_cv, u_cur, row, lane, acc);
        gather_row_h(bb_ptr, bb_cv, b_cur, row, lane, acc);
        sumbase = bS + (size_t)row * D;
        outrow  = out + (size_t)(NUSR + row) * D;
    } else {
        return;
    }

    float4 s = reinterpret_cast<const float4*>(sumbase)[lane];
    s.x += acc.x; s.y += acc.y; s.z += acc.z; s.w += acc.w;

    if (!final_layer) {
        // update running sum + write fp16 features for next layer
        float4* sump = const_cast<float4*>(reinterpret_cast<const float4*>(sumbase)) + lane;
        *sump = s;
        uint2 h;
        __half2 h0 = __float22half2_rn(make_float2(acc.x, acc.y));
        __half2 h1 = __float22half2_rn(make_float2(acc.z, acc.w));
        h.x = *reinterpret_cast<uint32_t*>(&h0);
        h.y = *reinterpret_cast<uint32_t*>(&h1);
        __half2* dst = (w < NUSR) ? u_new : b_new;
        *reinterpret_cast<uint2*>(dst + (size_t)row * DH + lane * 2) = h;
    } else {
        // fused epilogue: out = l2norm(s * 0.25)
        const float inv = 0.25f;
        s.x *= inv; s.y *= inv; s.z *= inv; s.w *= inv;
        float ss = s.x * s.x + s.y * s.y + s.z * s.z + s.w * s.w;
#pragma unroll
        for (int o = 16; o; o >>= 1) ss += __shfl_xor_sync(0xffffffffu, ss, o);
        float sc = 1.0f / fmaxf(sqrtf(ss), 1e-12f);
        s.x *= sc; s.y *= sc; s.z *= sc; s.w *= sc;
        reinterpret_cast<float4*>(outrow)[lane] = s;
    }
}

// ================= launcher ====================================================
extern "C" void kernel_launch(void* const* d_in, const int* in_sizes, int n_in,
                              void* d_out, int out_size) {
    const float* user_feat = (const float*)d_in[0];
    const float* biz_feat  = (const float*)d_in[1];
    const float* W_user    = (const float*)d_in[2];
    const float* W_biz     = (const float*)d_in[3];
    const int*   ub_u      = (const int*)  d_in[4];
    const int*   ub_b      = (const int*)  d_in[5];
    const float* val_ub    = (const float*)d_in[6];
    const float* val_bu    = (const float*)d_in[7];
    const int*   uu_src    = (const int*)  d_in[8];
    const int*   uu_dst    = (const int*)  d_in[9];
    const float* uu_val    = (const float*)d_in[10];
    const int*   bb_src    = (const int*)  d_in[11];
    const int*   bb_dst    = (const int*)  d_in[12];
    const float* bb_val    = (const float*)d_in[13];
    float* out = (float*)d_out;

    float *uS, *bS;
    __half2 *uhA, *uhB, *bhA, *bhB;
    cudaGetSymbolAddress((void**)&uS, g_uS);
    cudaGetSymbolAddress((void**)&bS, g_bS);
    cudaGetSymbolAddress((void**)&uhA, g_uhA);
    cudaGetSymbolAddress((void**)&uhB, g_uhB);
    cudaGetSymbolAddress((void**)&bhA, g_bhA);
    cudaGetSymbolAddress((void**)&bhB, g_bhB);

    int *bu_ptr, *uu_ptr, *ub_ptr, *bb_ptr, *cnt4, *part4;
    int2 *bu_cv, *uu_cv, *ub_cv, *bb_cv;
    cudaGetSymbolAddress((void**)&bu_ptr, g_bu_ptr);
    cudaGetSymbolAddress((void**)&bu_cv,  g_bu_cv);
    cudaGetSymbolAddress((void**)&uu_ptr, g_uu_ptr);
    cudaGetSymbolAddress((void**)&uu_cv,  g_uu_cv);
    cudaGetSymbolAddress((void**)&ub_ptr, g_ub_ptr);
    cudaGetSymbolAddress((void**)&ub_cv,  g_ub_cv);
    cudaGetSymbolAddress((void**)&bb_ptr, g_bb_ptr);
    cudaGetSymbolAddress((void**)&bb_cv,  g_bb_cv);
    cudaGetSymbolAddress((void**)&cnt4, g_cnt4);
    cudaGetSymbolAddress((void**)&part4, g_part4);

    static cudaStream_t s2 = nullptr;
    static cudaEvent_t evFork = nullptr, evJoin = nullptr;
    if (s2 == nullptr) {
        cudaStreamCreateWithFlags(&s2, cudaStreamNonBlocking);
        cudaEventCreateWithFlags(&evFork, cudaEventDisableTiming);
        cudaEventCreateWithFlags(&evJoin, cudaEventDisableTiming);
    }

    // ---- fork: CSR build chain on s2, GEMM chain on stream 0 ----
    cudaEventRecord(evFork, 0);
    cudaStreamWaitEvent(s2, evFork, 0);

    cudaMemsetAsync(cnt4, 0, CNT4_TOT * sizeof(int), s2);
    hist_all_kernel<<<(EALL + 255) / 256, 256, 0, s2>>>(ub_u, ub_b, uu_dst, bb_dst, cnt4);
    {
        dim3 g1((NUSR + SCAN_BLK - 1) / SCAN_BLK, 4);
        scan1_4_kernel<<<g1, SCAN_BLK, 0, s2>>>(cnt4, bu_ptr, uu_ptr, ub_ptr, bb_ptr, part4);
        dim3 g2(1, 4);
        scan2_4_kernel<<<g2, 128, 0, s2>>>(part4);
        dim3 g3((NUSR + 255) / 256, 4);
        scan3_4_kernel<<<g3, 256, 0, s2>>>(bu_ptr, uu_ptr, ub_ptr, bb_ptr, part4);
    }
    cudaMemsetAsync(cnt4, 0, CNT4_TOT * sizeof(int), s2);
    fill_all_kernel<<<(EALL + 255) / 256, 256, 0, s2>>>(
        ub_u, ub_b, val_ub, val_bu, uu_src, uu_dst, uu_val,
        bb_src, bb_dst, bb_val,
        bu_ptr, uu_ptr, ub_ptr, bb_ptr, cnt4,
        bu_cv, uu_cv, ub_cv, bb_cv);
    cudaEventRecord(evJoin, s2);

    // GEMM (+fused f2h) on stream 0, concurrent with CSR build
    gemm_tc_kernel<<<NUSR_PAD / GBM, 256>>>(user_feat, W_user, uS, uhA, NUSR);
    gemm_tc_kernel<<<NBIZ_PAD / GBM, 256>>>(biz_feat,  W_biz,  bS, bhA, NBIZ);

    // ---- join ----
    cudaStreamWaitEvent(0, evJoin, 0);

    __half2* u_cur = uhA; __half2* u_new = uhB;
    __half2* b_cur = bhA; __half2* b_new = bhB;

    const int totWarps = NUSR + NBIZ;
    const int spmmBlocks = (totWarps * 32 + 255) / 256;

    for (int layer = 0; layer < 3; layer++) {
        spmm_layer_kernel<<<spmmBlocks, 256>>>(
            bu_ptr, bu_cv, uu_ptr, uu_cv, ub_ptr, ub_cv, bb_ptr, bb_cv,
            u_cur, b_cur, u_new, b_new, uS, bS, out, layer == 2 ? 1 : 0);
        __half2* t;
        t = u_cur; u_cur = u_new; u_new = t;
        t = b_cur; b_cur = b_new; b_new = t;
    }
    (void)n_in; (void)in_sizes; (void)out_size;
}